// round 2
// baseline (speedup 1.0000x reference)
#include <cuda_runtime.h>
#include <cuda_bf16.h>
#include <cstdint>

// Problem dims
#define BDIM 32768
#define CDIM 1024
#define CHD  256
#define NDGI 512   // interleaved d/g width
#define RNK  16

// ---------------- scratch (__device__ globals; no runtime alloc) ----------------
__device__ __nv_bfloat16 g_t [BDIM*CDIM];   // LN output, bf16
__device__ __nv_bfloat16 g_h [BDIM*CHD];    // after gate
__device__ __nv_bfloat16 g_gl[BDIM*CHD];    // after GELU
__device__ __nv_bfloat16 g_u [BDIM*CHD];    // after W2eff
__device__ __nv_bfloat16 g_Wdg[NDGI*CDIM];  // interleaved, transposed [512][1024]
__device__ __nv_bfloat16 g_W1t[CHD*CHD];    // [n][k]
__device__ __nv_bfloat16 g_W2t[CHD*CHD];    // W2eff transposed [n][k]
__device__ __nv_bfloat16 g_Wut[CDIM*CHD];   // Wu_eff transposed [1024][256]
__device__ float g_Wvo[CHD*CHD];
__device__ float g_t1 [CHD*RNK];
__device__ float g_bdg[NDGI];
__device__ float g_b1e[CHD];
__device__ float g_b2e[CHD];
__device__ float g_bue[CDIM];

// ---------------- small helpers ----------------
__device__ __forceinline__ float sigm(float x) { return 1.f / (1.f + __expf(-x)); }
__device__ __forceinline__ float gelu_tanh(float x) {
    return 0.5f * x * (1.f + tanhf(0.7978845608028654f * (x + 0.044715f * x * x * x)));
}
__device__ __forceinline__ uint32_t smem_u32(const void* p) {
    return (uint32_t)__cvta_generic_to_shared(p);
}
__device__ __forceinline__ void cp16(uint32_t s, const void* g) {
    asm volatile("cp.async.cg.shared.global [%0], [%1], 16;\n" :: "r"(s), "l"(g));
}
__device__ __forceinline__ void cp_commit() { asm volatile("cp.async.commit_group;\n"); }
template <int N> __device__ __forceinline__ void cp_wait() {
    asm volatile("cp.async.wait_group %0;\n" :: "n"(N));
}

// ---------------- weight folding kernels (tiny) ----------------
// Wvo = Wv @ Wo  (256x256)
__global__ void k_wvo(const float* __restrict__ Wv, const float* __restrict__ Wo) {
    int i = blockIdx.x, n = threadIdx.x;
    float s = 0.f;
    for (int p = 0; p < CHD; p++) s += Wv[i*CHD + p] * Wo[p*CHD + n];
    g_Wvo[i*CHD + n] = s;
}

// W2eff^T[n][i] = sum_m W2[i][m] * Wvo[m][n]
__global__ void k_w2t(const float* __restrict__ W2) {
    int i = blockIdx.x, n = threadIdx.x;
    float s = 0.f;
    for (int m = 0; m < CHD; m++) s += W2[i*CHD + m] * g_Wvo[m*CHD + n];
    g_W2t[n*CHD + i] = __float2bfloat16(s);
}

// t1 = Wu @ Wld  (256x16)
__global__ void k_t1(const float* __restrict__ Wu, const float* __restrict__ Wld) {
    int r = blockIdx.x, i = threadIdx.x;
    float s = 0.f;
    for (int j = 0; j < CDIM; j++) s += Wu[(size_t)i*CDIM + j] * Wld[j*RNK + r];
    g_t1[i*RNK + r] = s;
}

// Wu_eff^T[n][i] = Wu[i][n] + sum_r t1[i][r]*Wlu[r][n]
__global__ void k_wut(const float* __restrict__ Wu, const float* __restrict__ Wlu) {
    int i = blockIdx.x, t = threadIdx.x;
    __shared__ float t1s[RNK];
    if (t < RNK) t1s[t] = g_t1[i*RNK + t];
    __syncthreads();
    for (int c = 0; c < 4; c++) {
        int n = c*256 + t;
        float v = Wu[(size_t)i*CDIM + n];
        #pragma unroll
        for (int r = 0; r < RNK; r++) v += t1s[r] * Wlu[r*CDIM + n];
        g_Wut[(size_t)n*CHD + i] = __float2bfloat16(v);
    }
}

// interleaved [n][k] : n=2j -> Wd[:,j]*dw_w[j], n=2j+1 -> Wg[:,j]
__global__ void k_wdg(const float* __restrict__ Wd, const float* __restrict__ Wg,
                      const float* __restrict__ dw_w) {
    int k = blockIdx.x, n = threadIdx.x, j = n >> 1;
    float v = (n & 1) ? Wg[k*CHD + j] : Wd[k*CHD + j] * dw_w[j];
    g_Wdg[(size_t)n*CDIM + k] = __float2bfloat16(v);
}

// W1^T[n][k]
__global__ void k_w1t(const float* __restrict__ W1) {
    int k = blockIdx.x, n = threadIdx.x;
    g_W1t[n*CHD + k] = __float2bfloat16(W1[k*CHD + n]);
}

// all bias vectors, single block of 1024 threads
__global__ void k_vecs(const float* __restrict__ bd, const float* __restrict__ bg,
                       const float* __restrict__ dw_w, const float* __restrict__ dw_b,
                       const float* __restrict__ W1, const float* __restrict__ b1,
                       const float* __restrict__ b2, const float* __restrict__ bv,
                       const float* __restrict__ Wo, const float* __restrict__ bo,
                       const float* __restrict__ bu, const float* __restrict__ Wld,
                       const float* __restrict__ Wlu) {
    int tid = threadIdx.x;
    __shared__ float s_tmpr[RNK];
    if (tid < NDGI) {
        int j = tid >> 1;
        g_bdg[tid] = (tid & 1) ? bg[j] : bd[j] * dw_w[j];
    }
    if (tid < CHD) {
        float s = 0.f;
        for (int k = 0; k < CHD; k++) s += dw_b[k] * W1[k*CHD + tid];
        g_b1e[tid] = b1[tid] + s;
        float s1 = 0.f, s2 = 0.f;
        for (int p = 0; p < CHD; p++) s1 += bv[p] * Wo[p*CHD + tid];
        for (int m = 0; m < CHD; m++) s2 += b2[m] * g_Wvo[m*CHD + tid];
        g_b2e[tid] = s1 + s2 + bo[tid];
    }
    if (tid < RNK) {
        float s = 0.f;
        for (int j = 0; j < CDIM; j++) s += bu[j] * Wld[j*RNK + tid];
        s_tmpr[tid] = s;
    }
    __syncthreads();
    {
        float s = 0.f;
        #pragma unroll
        for (int r = 0; r < RNK; r++) s += s_tmpr[r] * Wlu[r*CDIM + tid];
        g_bue[tid] = bu[tid] + s;
    }
}

// ---------------- LayerNorm -> bf16 ----------------
__global__ __launch_bounds__(256) void ln_k(const float* __restrict__ x,
                                            const float* __restrict__ lg,
                                            const float* __restrict__ lb) {
    int row = blockIdx.x, tid = threadIdx.x;
    const float4 v = reinterpret_cast<const float4*>(x)[(size_t)row*256 + tid];
    float s = v.x + v.y + v.z + v.w;
    float q = v.x*v.x + v.y*v.y + v.z*v.z + v.w*v.w;
    #pragma unroll
    for (int o = 16; o; o >>= 1) {
        s += __shfl_xor_sync(~0u, s, o);
        q += __shfl_xor_sync(~0u, q, o);
    }
    __shared__ float rs[8], rq[8], stats[2];
    int w = tid >> 5;
    if ((tid & 31) == 0) { rs[w] = s; rq[w] = q; }
    __syncthreads();
    if (tid == 0) {
        float S = 0.f, Q = 0.f;
        #pragma unroll
        for (int i = 0; i < 8; i++) { S += rs[i]; Q += rq[i]; }
        float mu = S * (1.f/1024.f);
        float var = Q * (1.f/1024.f) - mu*mu;
        stats[0] = mu; stats[1] = rsqrtf(var + 1e-5f);
    }
    __syncthreads();
    float mu = stats[0], rstd = stats[1];
    const float4 g4 = reinterpret_cast<const float4*>(lg)[tid];
    const float4 b4 = reinterpret_cast<const float4*>(lb)[tid];
    float t0 = (v.x-mu)*rstd*g4.x + b4.x;
    float t1 = (v.y-mu)*rstd*g4.y + b4.y;
    float t2 = (v.z-mu)*rstd*g4.z + b4.z;
    float t3 = (v.w-mu)*rstd*g4.w + b4.w;
    __nv_bfloat162 p0, p1;
    p0.x = __float2bfloat16(t0); p0.y = __float2bfloat16(t1);
    p1.x = __float2bfloat16(t2); p1.y = __float2bfloat16(t3);
    __nv_bfloat162* dst = reinterpret_cast<__nv_bfloat162*>(g_t + (size_t)row*CDIM);
    dst[2*tid]   = p0;
    dst[2*tid+1] = p1;
}

// ---------------- mma.sync bf16 GEMM, 128x64 tile, 2-stage cp.async ----------------
// SEL 0: g_t  @ g_Wdg (K=1024,N=512) -> gate  -> g_h   [B,256]
// SEL 1: g_h  @ g_W1t (K=256, N=256) -> gelu  -> g_gl
// SEL 2: g_gl @ g_W2t (K=256, N=256) -> bias  -> g_u
// SEL 3: g_u  @ g_Wut (K=256, N=1024)-> 0.5*(y)+0.5*x -> d_out (fp32)
template <int SEL>
__global__ __launch_bounds__(256) void gemm_k(float* __restrict__ outF,
                                              const float* __restrict__ xres) {
    constexpr int K = (SEL == 0) ? CDIM : CHD;
    const __nv_bfloat16* A  = (SEL==0) ? g_t   : (SEL==1) ? g_h   : (SEL==2) ? g_gl : g_u;
    const __nv_bfloat16* Bm = (SEL==0) ? g_Wdg : (SEL==1) ? g_W1t : (SEL==2) ? g_W2t : g_Wut;
    const float* bias       = (SEL==0) ? g_bdg : (SEL==1) ? g_b1e : (SEL==2) ? g_b2e : g_bue;

    __shared__ __align__(16) __nv_bfloat16 As[2][128][40];
    __shared__ __align__(16) __nv_bfloat16 Bs[2][64][40];

    const int tid = threadIdx.x;
    const int lane = tid & 31, warp = tid >> 5;
    const int wm = warp >> 1, wn = warp & 1;
    const int m0 = blockIdx.y * 128, n0 = blockIdx.x * 64;

    const int lrow = tid >> 2, lkc = tid & 3;  // loader mapping
    const __nv_bfloat16* Ag  = A  + (size_t)(m0 + lrow)      * K + lkc*8;
    const __nv_bfloat16* Ag2 = A  + (size_t)(m0 + lrow + 64) * K + lkc*8;
    const __nv_bfloat16* Bg  = Bm + (size_t)(n0 + lrow)      * K + lkc*8;
    uint32_t sA  = smem_u32(&As[0][lrow][lkc*8]);
    uint32_t sA2 = smem_u32(&As[0][lrow + 64][lkc*8]);
    uint32_t sB  = smem_u32(&Bs[0][lrow][lkc*8]);
    const uint32_t stA = 128*40*2, stB = 64*40*2;

    float acc[2][4][4] = {};
    constexpr int KT = K / 32;

    // prologue: stage 0
    cp16(sA,  Ag);  cp16(sA2, Ag2);  cp16(sB, Bg);
    cp_commit();

    for (int kt = 0; kt < KT; kt++) {
        int nb = (kt + 1) & 1;
        if (kt + 1 < KT) {
            cp16(sA  + nb*stA, Ag  + (kt+1)*32);
            cp16(sA2 + nb*stA, Ag2 + (kt+1)*32);
            cp16(sB  + nb*stB, Bg  + (kt+1)*32);
            cp_commit();
            cp_wait<1>();
        } else {
            cp_wait<0>();
        }
        __syncthreads();
        int buf = kt & 1;
        #pragma unroll
        for (int ks = 0; ks < 2; ks++) {
            uint32_t a[2][4], b[4][2];
            #pragma unroll
            for (int i = 0; i < 2; i++) {
                const __nv_bfloat16* p = &As[buf][wm*32 + i*16 + (lane & 15)][ks*16 + (lane >> 4)*8];
                asm volatile("ldmatrix.sync.aligned.m8n8.x4.shared.b16 {%0,%1,%2,%3},[%4];"
                             : "=r"(a[i][0]), "=r"(a[i][1]), "=r"(a[i][2]), "=r"(a[i][3])
                             : "r"(smem_u32(p)));
            }
            #pragma unroll
            for (int j = 0; j < 4; j++) {
                const __nv_bfloat16* p = &Bs[buf][wn*32 + j*8 + (lane & 7)][ks*16 + ((lane >> 3) & 1)*8];
                asm volatile("ldmatrix.sync.aligned.m8n8.x2.shared.b16 {%0,%1},[%2];"
                             : "=r"(b[j][0]), "=r"(b[j][1]) : "r"(smem_u32(p)));
            }
            #pragma unroll
            for (int i = 0; i < 2; i++)
                #pragma unroll
                for (int j = 0; j < 4; j++)
                    asm volatile("mma.sync.aligned.m16n8k16.row.col.f32.bf16.bf16.f32 "
                                 "{%0,%1,%2,%3},{%4,%5,%6,%7},{%8,%9},{%0,%1,%2,%3};"
                                 : "+f"(acc[i][j][0]), "+f"(acc[i][j][1]),
                                   "+f"(acc[i][j][2]), "+f"(acc[i][j][3])
                                 : "r"(a[i][0]), "r"(a[i][1]), "r"(a[i][2]), "r"(a[i][3]),
                                   "r"(b[j][0]), "r"(b[j][1]));
        }
        __syncthreads();
    }

    // epilogue
    #pragma unroll
    for (int i = 0; i < 2; i++) {
        #pragma unroll
        for (int j = 0; j < 4; j++) {
            int row = m0 + wm*32 + i*16 + (lane >> 2);
            int col = n0 + wn*32 + j*8 + (lane & 3)*2;
            float c0 = acc[i][j][0], c1 = acc[i][j][1];
            float c2 = acc[i][j][2], c3 = acc[i][j][3];
            if (SEL == 0) {
                float bdv = bias[col], bgv = bias[col + 1];
                float h0 = (c0 + bdv) * sigm(c1 + bgv);
                float h1 = (c2 + bdv) * sigm(c3 + bgv);
                g_h[(size_t)row*CHD + (col >> 1)]       = __float2bfloat16(h0);
                g_h[(size_t)(row + 8)*CHD + (col >> 1)] = __float2bfloat16(h1);
            } else if (SEL == 1 || SEL == 2) {
                float b0 = bias[col], b1v = bias[col + 1];
                float v0 = c0 + b0, v1 = c1 + b1v, v2 = c2 + b0, v3 = c3 + b1v;
                if (SEL == 1) {
                    v0 = gelu_tanh(v0); v1 = gelu_tanh(v1);
                    v2 = gelu_tanh(v2); v3 = gelu_tanh(v3);
                }
                __nv_bfloat16* dst = (SEL == 1) ? g_gl : g_u;
                __nv_bfloat162 p0, p1;
                p0.x = __float2bfloat16(v0); p0.y = __float2bfloat16(v1);
                p1.x = __float2bfloat16(v2); p1.y = __float2bfloat16(v3);
                *reinterpret_cast<__nv_bfloat162*>(dst + (size_t)row*CHD + col) = p0;
                *reinterpret_cast<__nv_bfloat162*>(dst + (size_t)(row + 8)*CHD + col) = p1;
            } else {
                float b0 = bias[col], b1v = bias[col + 1];
                const float2 x0 = *reinterpret_cast<const float2*>(xres + (size_t)row*CDIM + col);
                const float2 x1 = *reinterpret_cast<const float2*>(xres + (size_t)(row + 8)*CDIM + col);
                float2 o0, o1;
                o0.x = 0.5f*(c0 + b0)  + 0.5f*x0.x;
                o0.y = 0.5f*(c1 + b1v) + 0.5f*x0.y;
                o1.x = 0.5f*(c2 + b0)  + 0.5f*x1.x;
                o1.y = 0.5f*(c3 + b1v) + 0.5f*x1.y;
                *reinterpret_cast<float2*>(outF + (size_t)row*CDIM + col) = o0;
                *reinterpret_cast<float2*>(outF + (size_t)(row + 8)*CDIM + col) = o1;
            }
        }
    }
}

// ---------------- launch ----------------
extern "C" void kernel_launch(void* const* d_in, const int* in_sizes, int n_in,
                              void* d_out, int out_size) {
    const float* x    = (const float*)d_in[0];
    const float* ln_g = (const float*)d_in[1];
    const float* ln_b = (const float*)d_in[2];
    const float* Wd   = (const float*)d_in[3];
    const float* bd   = (const float*)d_in[4];
    const float* Wg   = (const float*)d_in[5];
    const float* bg   = (const float*)d_in[6];
    const float* dw_w = (const float*)d_in[7];
    const float* dw_b = (const float*)d_in[8];
    const float* W1   = (const float*)d_in[9];
    const float* b1   = (const float*)d_in[10];
    const float* W2   = (const float*)d_in[11];
    const float* b2   = (const float*)d_in[12];
    // d_in[13..16]: Wq, bq, Wk, bk — mathematically dead (softmax over 1 key == 1)
    const float* Wv   = (const float*)d_in[17];
    const float* bv   = (const float*)d_in[18];
    const float* Wo   = (const float*)d_in[19];
    const float* bo   = (const float*)d_in[20];
    const float* Wu   = (const float*)d_in[21];
    const float* bu   = (const float*)d_in[22];
    const float* Wld  = (const float*)d_in[23];
    const float* Wlu  = (const float*)d_in[24];
    float* out = (float*)d_out;

    // weight folding (all tiny)
    k_wvo<<<CHD, CHD>>>(Wv, Wo);
    k_vecs<<<1, 1024>>>(bd, bg, dw_w, dw_b, W1, b1, b2, bv, Wo, bo, bu, Wld, Wlu);
    k_w2t<<<CHD, CHD>>>(W2);
    k_t1<<<RNK, CHD>>>(Wu, Wld);
    k_wut<<<CHD, CHD>>>(Wu, Wlu);
    k_wdg<<<CDIM, NDGI>>>(Wd, Wg, dw_w);
    k_w1t<<<CHD, CHD>>>(W1);

    // main pipeline
    ln_k<<<BDIM, 256>>>(x, ln_g, ln_b);
    gemm_k<0><<<dim3(NDGI/64, BDIM/128), 256>>>(nullptr, nullptr);
    gemm_k<1><<<dim3(CHD/64,  BDIM/128), 256>>>(nullptr, nullptr);
    gemm_k<2><<<dim3(CHD/64,  BDIM/128), 256>>>(nullptr, nullptr);
    gemm_k<3><<<dim3(CDIM/64, BDIM/128), 256>>>(out, x);
}

// round 4
// speedup vs baseline: 2.1042x; 2.1042x over previous
#include <cuda_runtime.h>
#include <cuda_bf16.h>
#include <cstdint>

// Problem dims
#define BDIM 32768
#define CDIM 1024
#define CHD  256
#define NDGI 512   // interleaved d/g width
#define RNK  16

// ---------------- scratch (__device__ globals; no runtime alloc) ----------------
__device__ __nv_bfloat16 g_t [BDIM*CDIM];   // LN output, bf16
__device__ __nv_bfloat16 g_h [BDIM*CHD];    // after gate
__device__ __nv_bfloat16 g_gl[BDIM*CHD];    // after GELU
__device__ __nv_bfloat16 g_u [BDIM*CHD];    // after W2eff
__device__ __nv_bfloat16 g_Wdg[NDGI*CDIM];  // interleaved, transposed [512][1024]
__device__ __nv_bfloat16 g_W1t[CHD*CHD];    // [n][k]
__device__ __nv_bfloat16 g_W2t[CHD*CHD];    // W2eff transposed [n][k]
__device__ __nv_bfloat16 g_Wut[CDIM*CHD];   // Wu_eff transposed [1024][256]
__device__ float g_Wvo[CHD*CHD];
__device__ float g_t1 [CHD*RNK];
__device__ float g_bdg[NDGI];
__device__ float g_b1e[CHD];
__device__ float g_b2e[CHD];
__device__ float g_bue[CDIM];

// ---------------- small helpers ----------------
__device__ __forceinline__ float sigm(float x) { return 1.f / (1.f + __expf(-x)); }
__device__ __forceinline__ float gelu_tanh(float x) {
    return 0.5f * x * (1.f + tanhf(0.7978845608028654f * (x + 0.044715f * x * x * x)));
}
__device__ __forceinline__ uint32_t smem_u32(const void* p) {
    return (uint32_t)__cvta_generic_to_shared(p);
}
__device__ __forceinline__ void cp16(uint32_t s, const void* g) {
    asm volatile("cp.async.cg.shared.global [%0], [%1], 16;\n" :: "r"(s), "l"(g));
}
__device__ __forceinline__ void cp_commit() { asm volatile("cp.async.commit_group;\n"); }
template <int N> __device__ __forceinline__ void cp_wait() {
    asm volatile("cp.async.wait_group %0;\n" :: "n"(N));
}

// ---------------- weight folding kernels (parallelized) ----------------
// Wvo = Wv @ Wo  (256x256)
__global__ void k_wvo(const float* __restrict__ Wv, const float* __restrict__ Wo) {
    int i = blockIdx.x, n = threadIdx.x;
    float s0 = 0.f, s1 = 0.f, s2 = 0.f, s3 = 0.f;
    #pragma unroll 4
    for (int p = 0; p < CHD; p += 4) {
        s0 += Wv[i*CHD + p    ] * Wo[(p    )*CHD + n];
        s1 += Wv[i*CHD + p + 1] * Wo[(p + 1)*CHD + n];
        s2 += Wv[i*CHD + p + 2] * Wo[(p + 2)*CHD + n];
        s3 += Wv[i*CHD + p + 3] * Wo[(p + 3)*CHD + n];
    }
    g_Wvo[i*CHD + n] = (s0 + s1) + (s2 + s3);
}

// W2eff^T[n][i] = sum_m W2[i][m] * Wvo[m][n]
__global__ void k_w2t(const float* __restrict__ W2) {
    int i = blockIdx.x, n = threadIdx.x;
    float s0 = 0.f, s1 = 0.f, s2 = 0.f, s3 = 0.f;
    #pragma unroll 4
    for (int m = 0; m < CHD; m += 4) {
        s0 += W2[i*CHD + m    ] * g_Wvo[(m    )*CHD + n];
        s1 += W2[i*CHD + m + 1] * g_Wvo[(m + 1)*CHD + n];
        s2 += W2[i*CHD + m + 2] * g_Wvo[(m + 2)*CHD + n];
        s3 += W2[i*CHD + m + 3] * g_Wvo[(m + 3)*CHD + n];
    }
    g_W2t[n*CHD + i] = __float2bfloat16((s0 + s1) + (s2 + s3));
}

// t1 = Wu @ Wld  (256x16): block per i-row, warp per r, shuffle reduce
__global__ __launch_bounds__(512) void k_t1(const float* __restrict__ Wu,
                                            const float* __restrict__ Wld) {
    int i = blockIdx.x, tid = threadIdx.x;
    int w = tid >> 5, lane = tid & 31;
    __shared__ float row[CDIM];
    for (int j = tid; j < CDIM; j += 512) row[j] = Wu[(size_t)i*CDIM + j];
    __syncthreads();
    float s = 0.f;
    for (int j = lane; j < CDIM; j += 32) s += row[j] * Wld[j*RNK + w];
    #pragma unroll
    for (int o = 16; o; o >>= 1) s += __shfl_xor_sync(~0u, s, o);
    if (lane == 0) g_t1[i*RNK + w] = s;
}

// Wu_eff^T[n][i] = Wu[i][n] + sum_r t1[i][r]*Wlu[r][n]
__global__ void k_wut(const float* __restrict__ Wu, const float* __restrict__ Wlu) {
    int i = blockIdx.x, t = threadIdx.x;
    __shared__ float t1s[RNK];
    if (t < RNK) t1s[t] = g_t1[i*RNK + t];
    __syncthreads();
    for (int c = 0; c < 4; c++) {
        int n = c*256 + t;
        float v = Wu[(size_t)i*CDIM + n];
        #pragma unroll
        for (int r = 0; r < RNK; r++) v += t1s[r] * Wlu[r*CDIM + n];
        g_Wut[(size_t)n*CHD + i] = __float2bfloat16(v);
    }
}

// interleaved [n][k] : n=2j -> Wd[:,j]*dw_w[j], n=2j+1 -> Wg[:,j]
__global__ void k_wdg(const float* __restrict__ Wd, const float* __restrict__ Wg,
                      const float* __restrict__ dw_w) {
    int k = blockIdx.x, n = threadIdx.x, j = n >> 1;
    float v = (n & 1) ? Wg[k*CHD + j] : Wd[k*CHD + j] * dw_w[j];
    g_Wdg[(size_t)n*CDIM + k] = __float2bfloat16(v);
}

// W1^T[n][k]
__global__ void k_w1t(const float* __restrict__ W1) {
    int k = blockIdx.x, n = threadIdx.x;
    g_W1t[n*CHD + k] = __float2bfloat16(W1[k*CHD + n]);
}

// bias vectors, single block of 1024 threads (parallel reductions)
__global__ __launch_bounds__(1024) void k_vecs(
        const float* __restrict__ bd, const float* __restrict__ bg,
        const float* __restrict__ dw_w, const float* __restrict__ dw_b,
        const float* __restrict__ W1, const float* __restrict__ b1,
        const float* __restrict__ b2, const float* __restrict__ bv,
        const float* __restrict__ Wo, const float* __restrict__ bo,
        const float* __restrict__ bu, const float* __restrict__ Wld,
        const float* __restrict__ Wlu) {
    int tid = threadIdx.x;
    __shared__ float s_tmpr[RNK];
    if (tid < NDGI) {
        int j = tid >> 1;
        g_bdg[tid] = (tid & 1) ? bg[j] : bd[j] * dw_w[j];
    }
    // warps 0-15 reduce tmpr[r] = sum_j bu[j]*Wld[j][r]
    if (tid < 512) {
        int w = tid >> 5, lane = tid & 31;
        float s = 0.f;
        for (int j = lane; j < CDIM; j += 32) s += bu[j] * Wld[j*RNK + w];
        #pragma unroll
        for (int o = 16; o; o >>= 1) s += __shfl_xor_sync(~0u, s, o);
        if (lane == 0) s_tmpr[w] = s;
    }
    // threads 512-767 compute b1e/b2e for channel t
    if (tid >= 512 && tid < 768) {
        int t = tid - 512;
        float a0 = 0.f, a1 = 0.f, a2 = 0.f, a3 = 0.f;
        #pragma unroll 4
        for (int k = 0; k < CHD; k += 4) {
            a0 += dw_b[k    ] * W1[(k    )*CHD + t];
            a1 += dw_b[k + 1] * W1[(k + 1)*CHD + t];
            a2 += dw_b[k + 2] * W1[(k + 2)*CHD + t];
            a3 += dw_b[k + 3] * W1[(k + 3)*CHD + t];
        }
        g_b1e[t] = b1[t] + (a0 + a1) + (a2 + a3);
        float c0 = 0.f, c1 = 0.f, c2 = 0.f, c3 = 0.f;
        #pragma unroll 4
        for (int p = 0; p < CHD; p += 4) {
            c0 += bv[p    ] * Wo[(p    )*CHD + t] + b2[p    ] * g_Wvo[(p    )*CHD + t];
            c1 += bv[p + 1] * Wo[(p + 1)*CHD + t] + b2[p + 1] * g_Wvo[(p + 1)*CHD + t];
            c2 += bv[p + 2] * Wo[(p + 2)*CHD + t] + b2[p + 2] * g_Wvo[(p + 2)*CHD + t];
            c3 += bv[p + 3] * Wo[(p + 3)*CHD + t] + b2[p + 3] * g_Wvo[(p + 3)*CHD + t];
        }
        g_b2e[t] = (c0 + c1) + (c2 + c3) + bo[t];
    }
    __syncthreads();
    {
        float s = 0.f;
        #pragma unroll
        for (int r = 0; r < RNK; r++) s += s_tmpr[r] * Wlu[r*CDIM + tid];
        g_bue[tid] = bu[tid] + s;
    }
}

// ---------------- LayerNorm -> bf16 ----------------
__global__ __launch_bounds__(256) void ln_k(const float* __restrict__ x,
                                            const float* __restrict__ lg,
                                            const float* __restrict__ lb) {
    int row = blockIdx.x, tid = threadIdx.x;
    const float4 v = reinterpret_cast<const float4*>(x)[(size_t)row*256 + tid];
    float s = v.x + v.y + v.z + v.w;
    float q = v.x*v.x + v.y*v.y + v.z*v.z + v.w*v.w;
    #pragma unroll
    for (int o = 16; o; o >>= 1) {
        s += __shfl_xor_sync(~0u, s, o);
        q += __shfl_xor_sync(~0u, q, o);
    }
    __shared__ float rs[8], rq[8], stats[2];
    int w = tid >> 5;
    if ((tid & 31) == 0) { rs[w] = s; rq[w] = q; }
    __syncthreads();
    if (tid == 0) {
        float S = 0.f, Q = 0.f;
        #pragma unroll
        for (int i = 0; i < 8; i++) { S += rs[i]; Q += rq[i]; }
        float mu = S * (1.f/1024.f);
        float var = Q * (1.f/1024.f) - mu*mu;
        stats[0] = mu; stats[1] = rsqrtf(var + 1e-5f);
    }
    __syncthreads();
    float mu = stats[0], rstd = stats[1];
    const float4 g4 = reinterpret_cast<const float4*>(lg)[tid];
    const float4 b4 = reinterpret_cast<const float4*>(lb)[tid];
    float t0 = (v.x-mu)*rstd*g4.x + b4.x;
    float t1 = (v.y-mu)*rstd*g4.y + b4.y;
    float t2 = (v.z-mu)*rstd*g4.z + b4.z;
    float t3 = (v.w-mu)*rstd*g4.w + b4.w;
    __nv_bfloat162 p0, p1;
    p0.x = __float2bfloat16(t0); p0.y = __float2bfloat16(t1);
    p1.x = __float2bfloat16(t2); p1.y = __float2bfloat16(t3);
    __nv_bfloat162* dst = reinterpret_cast<__nv_bfloat162*>(g_t + (size_t)row*CDIM);
    dst[2*tid]   = p0;
    dst[2*tid+1] = p1;
}

// ---------------- mma.sync bf16 GEMM, 128x128 tile, 2-stage cp.async ----------------
// SEL 0: g_t  @ g_Wdg (K=1024,N=512) -> gate  -> g_h   [B,256]
// SEL 1: g_h  @ g_W1t (K=256, N=256) -> gelu  -> g_gl
// SEL 2: g_gl @ g_W2t (K=256, N=256) -> bias  -> g_u
// SEL 3: g_u  @ g_Wut (K=256, N=1024)-> 0.5*(y)+0.5*x -> d_out (fp32)
template <int SEL>
__global__ __launch_bounds__(256) void gemm_k(float* __restrict__ outF,
                                              const float* __restrict__ xres) {
    constexpr int K = (SEL == 0) ? CDIM : CHD;
    const __nv_bfloat16* A  = (SEL==0) ? g_t   : (SEL==1) ? g_h   : (SEL==2) ? g_gl : g_u;
    const __nv_bfloat16* Bm = (SEL==0) ? g_Wdg : (SEL==1) ? g_W1t : (SEL==2) ? g_W2t : g_Wut;
    const float* bias       = (SEL==0) ? g_bdg : (SEL==1) ? g_b1e : (SEL==2) ? g_b2e : g_bue;

    __shared__ __align__(16) __nv_bfloat16 As[2][128][40];
    __shared__ __align__(16) __nv_bfloat16 Bs[2][128][40];

    const int tid = threadIdx.x;
    const int lane = tid & 31, warp = tid >> 5;
    const int wm = warp >> 1, wn = warp & 1;
    const int m0 = blockIdx.y * 128, n0 = blockIdx.x * 128;

    // loader: each thread moves 2 x 16B for A and 2 x 16B for B per stage
    const int lrow = tid >> 2, lkc = tid & 3;  // 64 rows x 4 chunks per 256 threads
    const __nv_bfloat16* Ag  = A  + (size_t)(m0 + lrow)      * K + lkc*8;
    const __nv_bfloat16* Ag2 = A  + (size_t)(m0 + lrow + 64) * K + lkc*8;
    const __nv_bfloat16* Bg  = Bm + (size_t)(n0 + lrow)      * K + lkc*8;
    const __nv_bfloat16* Bg2 = Bm + (size_t)(n0 + lrow + 64) * K + lkc*8;
    uint32_t sA  = smem_u32(&As[0][lrow][lkc*8]);
    uint32_t sA2 = smem_u32(&As[0][lrow + 64][lkc*8]);
    uint32_t sB  = smem_u32(&Bs[0][lrow][lkc*8]);
    uint32_t sB2 = smem_u32(&Bs[0][lrow + 64][lkc*8]);
    const uint32_t stA = 128*40*2, stB = 128*40*2;

    float acc[2][8][4] = {};
    constexpr int KT = K / 32;

    // prologue: stage 0
    cp16(sA, Ag); cp16(sA2, Ag2); cp16(sB, Bg); cp16(sB2, Bg2);
    cp_commit();

    for (int kt = 0; kt < KT; kt++) {
        int nb = (kt + 1) & 1;
        if (kt + 1 < KT) {
            cp16(sA  + nb*stA, Ag  + (kt+1)*32);
            cp16(sA2 + nb*stA, Ag2 + (kt+1)*32);
            cp16(sB  + nb*stB, Bg  + (kt+1)*32);
            cp16(sB2 + nb*stB, Bg2 + (kt+1)*32);
            cp_commit();
            cp_wait<1>();
        } else {
            cp_wait<0>();
        }
        __syncthreads();
        int buf = kt & 1;
        #pragma unroll
        for (int ks = 0; ks < 2; ks++) {
            uint32_t a[2][4], b[8][2];
            #pragma unroll
            for (int i = 0; i < 2; i++) {
                const __nv_bfloat16* p = &As[buf][wm*32 + i*16 + (lane & 15)][ks*16 + (lane >> 4)*8];
                asm volatile("ldmatrix.sync.aligned.m8n8.x4.shared.b16 {%0,%1,%2,%3},[%4];"
                             : "=r"(a[i][0]), "=r"(a[i][1]), "=r"(a[i][2]), "=r"(a[i][3])
                             : "r"(smem_u32(p)));
            }
            #pragma unroll
            for (int j = 0; j < 8; j++) {
                const __nv_bfloat16* p = &Bs[buf][wn*64 + j*8 + (lane & 7)][ks*16 + ((lane >> 3) & 1)*8];
                asm volatile("ldmatrix.sync.aligned.m8n8.x2.shared.b16 {%0,%1},[%2];"
                             : "=r"(b[j][0]), "=r"(b[j][1]) : "r"(smem_u32(p)));
            }
            #pragma unroll
            for (int i = 0; i < 2; i++)
                #pragma unroll
                for (int j = 0; j < 8; j++)
                    asm volatile("mma.sync.aligned.m16n8k16.row.col.f32.bf16.bf16.f32 "
                                 "{%0,%1,%2,%3},{%4,%5,%6,%7},{%8,%9},{%0,%1,%2,%3};"
                                 : "+f"(acc[i][j][0]), "+f"(acc[i][j][1]),
                                   "+f"(acc[i][j][2]), "+f"(acc[i][j][3])
                                 : "r"(a[i][0]), "r"(a[i][1]), "r"(a[i][2]), "r"(a[i][3]),
                                   "r"(b[j][0]), "r"(b[j][1]));
        }
        __syncthreads();
    }

    // epilogue
    #pragma unroll
    for (int i = 0; i < 2; i++) {
        #pragma unroll
        for (int j = 0; j < 8; j++) {
            int row = m0 + wm*32 + i*16 + (lane >> 2);
            int col = n0 + wn*64 + j*8 + (lane & 3)*2;
            float c0 = acc[i][j][0], c1 = acc[i][j][1];
            float c2 = acc[i][j][2], c3 = acc[i][j][3];
            if (SEL == 0) {
                float bdv = bias[col], bgv = bias[col + 1];
                float h0 = (c0 + bdv) * sigm(c1 + bgv);
                float h1 = (c2 + bdv) * sigm(c3 + bgv);
                g_h[(size_t)row*CHD + (col >> 1)]       = __float2bfloat16(h0);
                g_h[(size_t)(row + 8)*CHD + (col >> 1)] = __float2bfloat16(h1);
            } else if (SEL == 1 || SEL == 2) {
                float b0 = bias[col], b1v = bias[col + 1];
                float v0 = c0 + b0, v1 = c1 + b1v, v2 = c2 + b0, v3 = c3 + b1v;
                if (SEL == 1) {
                    v0 = gelu_tanh(v0); v1 = gelu_tanh(v1);
                    v2 = gelu_tanh(v2); v3 = gelu_tanh(v3);
                }
                __nv_bfloat16* dst = (SEL == 1) ? g_gl : g_u;
                __nv_bfloat162 p0, p1;
                p0.x = __float2bfloat16(v0); p0.y = __float2bfloat16(v1);
                p1.x = __float2bfloat16(v2); p1.y = __float2bfloat16(v3);
                *reinterpret_cast<__nv_bfloat162*>(dst + (size_t)row*CHD + col) = p0;
                *reinterpret_cast<__nv_bfloat162*>(dst + (size_t)(row + 8)*CHD + col) = p1;
            } else {
                float b0 = bias[col], b1v = bias[col + 1];
                const float2 x0 = *reinterpret_cast<const float2*>(xres + (size_t)row*CDIM + col);
                const float2 x1 = *reinterpret_cast<const float2*>(xres + (size_t)(row + 8)*CDIM + col);
                float2 o0, o1;
                o0.x = 0.5f*(c0 + b0)  + 0.5f*x0.x;
                o0.y = 0.5f*(c1 + b1v) + 0.5f*x0.y;
                o1.x = 0.5f*(c2 + b0)  + 0.5f*x1.x;
                o1.y = 0.5f*(c3 + b1v) + 0.5f*x1.y;
                *reinterpret_cast<float2*>(outF + (size_t)row*CDIM + col) = o0;
                *reinterpret_cast<float2*>(outF + (size_t)(row + 8)*CDIM + col) = o1;
            }
        }
    }
}

// ---------------- launch ----------------
extern "C" void kernel_launch(void* const* d_in, const int* in_sizes, int n_in,
                              void* d_out, int out_size) {
    const float* x    = (const float*)d_in[0];
    const float* ln_g = (const float*)d_in[1];
    const float* ln_b = (const float*)d_in[2];
    const float* Wd   = (const float*)d_in[3];
    const float* bd   = (const float*)d_in[4];
    const float* Wg   = (const float*)d_in[5];
    const float* bg   = (const float*)d_in[6];
    const float* dw_w = (const float*)d_in[7];
    const float* dw_b = (const float*)d_in[8];
    const float* W1   = (const float*)d_in[9];
    const float* b1   = (const float*)d_in[10];
    const float* W2   = (const float*)d_in[11];
    const float* b2   = (const float*)d_in[12];
    // d_in[13..16]: Wq, bq, Wk, bk — dead (softmax over 1 key == 1)
    const float* Wv   = (const float*)d_in[17];
    const float* bv   = (const float*)d_in[18];
    const float* Wo   = (const float*)d_in[19];
    const float* bo   = (const float*)d_in[20];
    const float* Wu   = (const float*)d_in[21];
    const float* bu   = (const float*)d_in[22];
    const float* Wld  = (const float*)d_in[23];
    const float* Wlu  = (const float*)d_in[24];
    float* out = (float*)d_out;

    // weight folding (tiny, now parallel)
    k_wvo<<<CHD, CHD>>>(Wv, Wo);
    k_t1 <<<CHD, 512>>>(Wu, Wld);
    k_vecs<<<1, 1024>>>(bd, bg, dw_w, dw_b, W1, b1, b2, bv, Wo, bo, bu, Wld, Wlu);
    k_w2t<<<CHD, CHD>>>(W2);
    k_wut<<<CHD, CHD>>>(Wu, Wlu);
    k_wdg<<<CDIM, NDGI>>>(Wd, Wg, dw_w);
    k_w1t<<<CHD, CHD>>>(W1);

    // main pipeline
    ln_k<<<BDIM, 256>>>(x, ln_g, ln_b);
    gemm_k<0><<<dim3(NDGI/128, BDIM/128), 256>>>(nullptr, nullptr);
    gemm_k<1><<<dim3(CHD/128,  BDIM/128), 256>>>(nullptr, nullptr);
    gemm_k<2><<<dim3(CHD/128,  BDIM/128), 256>>>(nullptr, nullptr);
    gemm_k<3><<<dim3(CDIM/128, BDIM/128), 256>>>(out, x);
}

// round 5
// speedup vs baseline: 2.1520x; 1.0227x over previous
#include <cuda_runtime.h>
#include <cuda_bf16.h>
#include <cstdint>

// Problem dims
#define BDIM 32768
#define CDIM 1024
#define CHD  256
#define NDGI 512   // interleaved d/g width
#define RNK  16

// ---------------- scratch (__device__ globals; no runtime alloc) ----------------
__device__ __nv_bfloat16 g_t [BDIM*CDIM];   // LN output, bf16
__device__ __nv_bfloat16 g_h [BDIM*CHD];    // after gate
__device__ __nv_bfloat16 g_gl[BDIM*CHD];    // after GELU
__device__ __nv_bfloat16 g_u [BDIM*CHD];    // after W2eff
__device__ __nv_bfloat16 g_Wdg[NDGI*CDIM];  // interleaved, transposed [512][1024]
__device__ __nv_bfloat16 g_W1t[CHD*CHD];    // [n][k]
__device__ __nv_bfloat16 g_W2t[CHD*CHD];    // W2eff transposed [n][k]
__device__ __nv_bfloat16 g_Wut[CDIM*CHD];   // Wu_eff transposed [1024][256]
__device__ float g_Wvo[CHD*CHD];
__device__ float g_t1 [CHD*RNK];
__device__ float g_tmpr[RNK];
__device__ float g_bdg[NDGI];
__device__ float g_b1e[CHD];
__device__ float g_b2e[CHD];
__device__ float g_bue[CDIM];

// ---------------- small helpers ----------------
__device__ __forceinline__ float sigm(float x) { return 1.f / (1.f + __expf(-x)); }
__device__ __forceinline__ float gelu_tanh(float x) {
    return 0.5f * x * (1.f + tanhf(0.7978845608028654f * (x + 0.044715f * x * x * x)));
}
__device__ __forceinline__ uint32_t smem_u32(const void* p) {
    return (uint32_t)__cvta_generic_to_shared(p);
}
__device__ __forceinline__ void cp16(uint32_t s, const void* g) {
    asm volatile("cp.async.cg.shared.global [%0], [%1], 16;\n" :: "r"(s), "l"(g));
}
__device__ __forceinline__ void cp_commit() { asm volatile("cp.async.commit_group;\n"); }
template <int N> __device__ __forceinline__ void cp_wait() {
    asm volatile("cp.async.wait_group %0;\n" :: "n"(N));
}

// ---------------- weight folding (high-MLP versions) ----------------
// Wvo = Wv @ Wo  (256x256, K=256). Block: 8 i-rows staged in smem, thread = n.
__global__ __launch_bounds__(256) void k_wvo(const float* __restrict__ Wv,
                                             const float* __restrict__ Wo) {
    const int ib = blockIdx.x * 8, n = threadIdx.x;
    __shared__ float s_wv[8][CHD];
    for (int t = n; t < 8*CHD; t += 256) s_wv[t >> 8][t & 255] = Wv[(ib + (t >> 8))*CHD + (t & 255)];
    __syncthreads();
    float acc[8] = {};
    #pragma unroll 4
    for (int p = 0; p < CHD; p++) {
        float wo = Wo[p*CHD + n];
        #pragma unroll
        for (int r = 0; r < 8; r++) acc[r] += s_wv[r][p] * wo;
    }
    #pragma unroll
    for (int r = 0; r < 8; r++) g_Wvo[(ib + r)*CHD + n] = acc[r];
}

// W2eff^T[n][i] = sum_m W2[i][m]*Wvo[m][n]; 8 i-rows per block, packed 16B write.
__global__ __launch_bounds__(256) void k_w2t(const float* __restrict__ W2) {
    const int ib = blockIdx.x * 8, n = threadIdx.x;
    __shared__ float s_w2[8][CHD];
    for (int t = n; t < 8*CHD; t += 256) s_w2[t >> 8][t & 255] = W2[(ib + (t >> 8))*CHD + (t & 255)];
    __syncthreads();
    float acc[8] = {};
    #pragma unroll 4
    for (int m = 0; m < CHD; m++) {
        float wv = g_Wvo[m*CHD + n];
        #pragma unroll
        for (int r = 0; r < 8; r++) acc[r] += s_w2[r][m] * wv;
    }
    __nv_bfloat16 pk[8];
    #pragma unroll
    for (int r = 0; r < 8; r++) pk[r] = __float2bfloat16(acc[r]);
    *reinterpret_cast<uint4*>(&g_W2t[n*CHD + ib]) = *reinterpret_cast<uint4*>(pk);
}

// t1 = Wu @ Wld  (256x16): block per i-row, warp per r, shuffle reduce
__global__ __launch_bounds__(512) void k_t1(const float* __restrict__ Wu,
                                            const float* __restrict__ Wld) {
    int i = blockIdx.x, tid = threadIdx.x;
    int w = tid >> 5, lane = tid & 31;
    __shared__ float row[CDIM];
    for (int j = tid; j < CDIM; j += 512) row[j] = Wu[(size_t)i*CDIM + j];
    __syncthreads();
    float s = 0.f;
    for (int j = lane; j < CDIM; j += 32) s += row[j] * Wld[j*RNK + w];
    #pragma unroll
    for (int o = 16; o; o >>= 1) s += __shfl_xor_sync(~0u, s, o);
    if (lane == 0) g_t1[i*RNK + w] = s;
}

// Wu_eff^T[n][i]: block = n (1024), thread = i (256). Coalesced bf16 writes.
__global__ __launch_bounds__(256) void k_wut(const float* __restrict__ Wu,
                                             const float* __restrict__ Wlu) {
    const int n = blockIdx.x, i = threadIdx.x;
    float v = Wu[(size_t)i*CDIM + n];
    const float* t1r = &g_t1[i*RNK];
    #pragma unroll
    for (int r = 0; r < RNK; r++) v += t1r[r] * Wlu[r*CDIM + n];
    g_Wut[(size_t)n*CHD + i] = __float2bfloat16(v);
}

// interleaved [n][k]: block = n (512), threads sweep k. Coalesced writes.
__global__ __launch_bounds__(256) void k_wdg(const float* __restrict__ Wd,
                                             const float* __restrict__ Wg,
                                             const float* __restrict__ dw_w) {
    const int n = blockIdx.x, j = n >> 1;
    const bool isg = (n & 1);
    const float scale = isg ? 1.f : dw_w[j];
    const float* src = isg ? Wg : Wd;
    #pragma unroll
    for (int c = 0; c < 4; c++) {
        int k = c*256 + threadIdx.x;
        g_Wdg[(size_t)n*CDIM + k] = __float2bfloat16(src[(size_t)k*CHD + j] * scale);
    }
}

// W1^T: block = n, thread = k. Coalesced writes.
__global__ __launch_bounds__(256) void k_w1t(const float* __restrict__ W1) {
    const int n = blockIdx.x, k = threadIdx.x;
    g_W1t[n*CHD + k] = __float2bfloat16(W1[k*CHD + n]);
}

// b1e/b2e/bdg: block = t (256), 4 warps split the reductions.
__global__ __launch_bounds__(128) void k_b12(
        const float* __restrict__ dw_b, const float* __restrict__ W1,
        const float* __restrict__ b1,  const float* __restrict__ bv,
        const float* __restrict__ Wo,  const float* __restrict__ b2,
        const float* __restrict__ bo,  const float* __restrict__ bd,
        const float* __restrict__ bg,  const float* __restrict__ dw_w) {
    const int t = blockIdx.x, tid = threadIdx.x;
    const int w = tid >> 5, lane = tid & 31;
    __shared__ float part[4];
    float s = 0.f;
    if (w == 0)      for (int k = lane; k < CHD; k += 32) s += dw_b[k] * W1[k*CHD + t];
    else if (w == 1) for (int p = lane; p < CHD; p += 32) s += bv[p] * Wo[p*CHD + t];
    else if (w == 2) for (int m = lane; m < CHD; m += 32) s += b2[m] * g_Wvo[m*CHD + t];
    #pragma unroll
    for (int o = 16; o; o >>= 1) s += __shfl_xor_sync(~0u, s, o);
    if (lane == 0) part[w] = s;
    __syncthreads();
    if (tid == 0) {
        g_b1e[t] = b1[t] + part[0];
        g_b2e[t] = part[1] + part[2] + bo[t];
    }
    if (tid == 96) {  // warp 3 lane 0
        g_bdg[2*t]     = bd[t] * dw_w[t];
        g_bdg[2*t + 1] = bg[t];
    }
}

// tmpr[r] = sum_j bu[j]*Wld[j][r]
__global__ __launch_bounds__(256) void k_bue1(const float* __restrict__ bu,
                                              const float* __restrict__ Wld) {
    const int r = blockIdx.x, tid = threadIdx.x;
    float s = 0.f;
    for (int j = tid; j < CDIM; j += 256) s += bu[j] * Wld[j*RNK + r];
    #pragma unroll
    for (int o = 16; o; o >>= 1) s += __shfl_xor_sync(~0u, s, o);
    __shared__ float ws[8];
    if ((tid & 31) == 0) ws[tid >> 5] = s;
    __syncthreads();
    if (tid == 0) {
        float S = 0.f;
        #pragma unroll
        for (int i = 0; i < 8; i++) S += ws[i];
        g_tmpr[r] = S;
    }
}

// bue[n] = bu[n] + tmpr @ Wlu[:,n]
__global__ __launch_bounds__(256) void k_bue2(const float* __restrict__ bu,
                                              const float* __restrict__ Wlu) {
    const int n = blockIdx.x*256 + threadIdx.x;
    float v = bu[n];
    #pragma unroll
    for (int r = 0; r < RNK; r++) v += g_tmpr[r] * Wlu[r*CDIM + n];
    g_bue[n] = v;
}

// ---------------- LayerNorm -> bf16 ----------------
__global__ __launch_bounds__(256) void ln_k(const float* __restrict__ x,
                                            const float* __restrict__ lg,
                                            const float* __restrict__ lb) {
    int row = blockIdx.x, tid = threadIdx.x;
    const float4 v = reinterpret_cast<const float4*>(x)[(size_t)row*256 + tid];
    float s = v.x + v.y + v.z + v.w;
    float q = v.x*v.x + v.y*v.y + v.z*v.z + v.w*v.w;
    #pragma unroll
    for (int o = 16; o; o >>= 1) {
        s += __shfl_xor_sync(~0u, s, o);
        q += __shfl_xor_sync(~0u, q, o);
    }
    __shared__ float rs[8], rq[8], stats[2];
    int w = tid >> 5;
    if ((tid & 31) == 0) { rs[w] = s; rq[w] = q; }
    __syncthreads();
    if (tid == 0) {
        float S = 0.f, Q = 0.f;
        #pragma unroll
        for (int i = 0; i < 8; i++) { S += rs[i]; Q += rq[i]; }
        float mu = S * (1.f/1024.f);
        float var = Q * (1.f/1024.f) - mu*mu;
        stats[0] = mu; stats[1] = rsqrtf(var + 1e-5f);
    }
    __syncthreads();
    float mu = stats[0], rstd = stats[1];
    const float4 g4 = reinterpret_cast<const float4*>(lg)[tid];
    const float4 b4 = reinterpret_cast<const float4*>(lb)[tid];
    float t0 = (v.x-mu)*rstd*g4.x + b4.x;
    float t1 = (v.y-mu)*rstd*g4.y + b4.y;
    float t2 = (v.z-mu)*rstd*g4.z + b4.z;
    float t3 = (v.w-mu)*rstd*g4.w + b4.w;
    __nv_bfloat162 p0, p1;
    p0.x = __float2bfloat16(t0); p0.y = __float2bfloat16(t1);
    p1.x = __float2bfloat16(t2); p1.y = __float2bfloat16(t3);
    __nv_bfloat162* dst = reinterpret_cast<__nv_bfloat162*>(g_t + (size_t)row*CDIM);
    dst[2*tid]   = p0;
    dst[2*tid+1] = p1;
}

// ---------------- mma.sync bf16 GEMM, 128x128 tile, 3-stage, 1 sync/iter ----------------
#define STG_A (128*40)          // elements per A stage
#define STG_B (128*40)
#define SMEM_BYTES (3*(STG_A + STG_B)*2)

template <int SEL>
__global__ __launch_bounds__(256) void gemm_k(float* __restrict__ outF,
                                              const float* __restrict__ xres) {
    constexpr int K = (SEL == 0) ? CDIM : CHD;
    const __nv_bfloat16* A  = (SEL==0) ? g_t   : (SEL==1) ? g_h   : (SEL==2) ? g_gl : g_u;
    const __nv_bfloat16* Bm = (SEL==0) ? g_Wdg : (SEL==1) ? g_W1t : (SEL==2) ? g_W2t : g_Wut;
    const float* bias       = (SEL==0) ? g_bdg : (SEL==1) ? g_b1e : (SEL==2) ? g_b2e : g_bue;

    extern __shared__ __align__(16) __nv_bfloat16 smem[];
    __nv_bfloat16* Abase = smem;                 // 3 stages of [128][40]
    __nv_bfloat16* Bbase = smem + 3*STG_A;

    const int tid = threadIdx.x;
    const int lane = tid & 31, warp = tid >> 5;
    const int wm = warp >> 1, wn = warp & 1;
    const int m0 = blockIdx.y * 128, n0 = blockIdx.x * 128;

    // loaders: 64 rows x 4 k-chunks per 256 threads; 2 row-halves for A and B
    const int lrow = tid >> 2, lkc = tid & 3;
    const __nv_bfloat16* Ag  = A  + (size_t)(m0 + lrow)      * K + lkc*8;
    const __nv_bfloat16* Ag2 = A  + (size_t)(m0 + lrow + 64) * K + lkc*8;
    const __nv_bfloat16* Bg  = Bm + (size_t)(n0 + lrow)      * K + lkc*8;
    const __nv_bfloat16* Bg2 = Bm + (size_t)(n0 + lrow + 64) * K + lkc*8;
    const uint32_t sA  = smem_u32(Abase + lrow*40 + lkc*8);
    const uint32_t sA2 = smem_u32(Abase + (lrow + 64)*40 + lkc*8);
    const uint32_t sB  = smem_u32(Bbase + lrow*40 + lkc*8);
    const uint32_t sB2 = smem_u32(Bbase + (lrow + 64)*40 + lkc*8);
    const uint32_t stS = STG_A*2;  // bytes per stage

    float acc[2][8][4] = {};
    constexpr int KT = K / 32;

    // prologue: stages 0 and 1
    cp16(sA, Ag); cp16(sA2, Ag2); cp16(sB, Bg); cp16(sB2, Bg2);
    cp_commit();
    cp16(sA + stS, Ag + 32); cp16(sA2 + stS, Ag2 + 32);
    cp16(sB + stS, Bg + 32); cp16(sB2 + stS, Bg2 + 32);
    cp_commit();

    int buf = 0;
    for (int kt = 0; kt < KT; kt++) {
        if (kt == KT - 1) cp_wait<0>(); else cp_wait<1>();
        __syncthreads();
        if (kt + 2 < KT) {
            int wb = (buf + 2 >= 3) ? buf - 1 : buf + 2;
            cp16(sA  + wb*stS, Ag  + (kt+2)*32);
            cp16(sA2 + wb*stS, Ag2 + (kt+2)*32);
            cp16(sB  + wb*stS, Bg  + (kt+2)*32);
            cp16(sB2 + wb*stS, Bg2 + (kt+2)*32);
            cp_commit();
        }
        const __nv_bfloat16* Asb = Abase + buf*STG_A;
        const __nv_bfloat16* Bsb = Bbase + buf*STG_B;
        #pragma unroll
        for (int ks = 0; ks < 2; ks++) {
            uint32_t a[2][4], b[8][2];
            #pragma unroll
            for (int i = 0; i < 2; i++) {
                const __nv_bfloat16* p = Asb + (wm*32 + i*16 + (lane & 15))*40 + ks*16 + (lane >> 4)*8;
                asm volatile("ldmatrix.sync.aligned.m8n8.x4.shared.b16 {%0,%1,%2,%3},[%4];"
                             : "=r"(a[i][0]), "=r"(a[i][1]), "=r"(a[i][2]), "=r"(a[i][3])
                             : "r"(smem_u32(p)));
            }
            #pragma unroll
            for (int j = 0; j < 8; j++) {
                const __nv_bfloat16* p = Bsb + (wn*64 + j*8 + (lane & 7))*40 + ks*16 + ((lane >> 3) & 1)*8;
                asm volatile("ldmatrix.sync.aligned.m8n8.x2.shared.b16 {%0,%1},[%2];"
                             : "=r"(b[j][0]), "=r"(b[j][1]) : "r"(smem_u32(p)));
            }
            #pragma unroll
            for (int i = 0; i < 2; i++)
                #pragma unroll
                for (int j = 0; j < 8; j++)
                    asm volatile("mma.sync.aligned.m16n8k16.row.col.f32.bf16.bf16.f32 "
                                 "{%0,%1,%2,%3},{%4,%5,%6,%7},{%8,%9},{%0,%1,%2,%3};"
                                 : "+f"(acc[i][j][0]), "+f"(acc[i][j][1]),
                                   "+f"(acc[i][j][2]), "+f"(acc[i][j][3])
                                 : "r"(a[i][0]), "r"(a[i][1]), "r"(a[i][2]), "r"(a[i][3]),
                                   "r"(b[j][0]), "r"(b[j][1]));
        }
        buf = (buf + 1 >= 3) ? 0 : buf + 1;
    }

    // epilogue
    #pragma unroll
    for (int i = 0; i < 2; i++) {
        #pragma unroll
        for (int j = 0; j < 8; j++) {
            int row = m0 + wm*32 + i*16 + (lane >> 2);
            int col = n0 + wn*64 + j*8 + (lane & 3)*2;
            float c0 = acc[i][j][0], c1 = acc[i][j][1];
            float c2 = acc[i][j][2], c3 = acc[i][j][3];
            if (SEL == 0) {
                float bdv = bias[col], bgv = bias[col + 1];
                float h0 = (c0 + bdv) * sigm(c1 + bgv);
                float h1 = (c2 + bdv) * sigm(c3 + bgv);
                g_h[(size_t)row*CHD + (col >> 1)]       = __float2bfloat16(h0);
                g_h[(size_t)(row + 8)*CHD + (col >> 1)] = __float2bfloat16(h1);
            } else if (SEL == 1 || SEL == 2) {
                float b0 = bias[col], b1v = bias[col + 1];
                float v0 = c0 + b0, v1 = c1 + b1v, v2 = c2 + b0, v3 = c3 + b1v;
                if (SEL == 1) {
                    v0 = gelu_tanh(v0); v1 = gelu_tanh(v1);
                    v2 = gelu_tanh(v2); v3 = gelu_tanh(v3);
                }
                __nv_bfloat16* dst = (SEL == 1) ? g_gl : g_u;
                __nv_bfloat162 p0, p1;
                p0.x = __float2bfloat16(v0); p0.y = __float2bfloat16(v1);
                p1.x = __float2bfloat16(v2); p1.y = __float2bfloat16(v3);
                *reinterpret_cast<__nv_bfloat162*>(dst + (size_t)row*CHD + col) = p0;
                *reinterpret_cast<__nv_bfloat162*>(dst + (size_t)(row + 8)*CHD + col) = p1;
            } else {
                float b0 = bias[col], b1v = bias[col + 1];
                const float2 x0 = *reinterpret_cast<const float2*>(xres + (size_t)row*CDIM + col);
                const float2 x1 = *reinterpret_cast<const float2*>(xres + (size_t)(row + 8)*CDIM + col);
                float2 o0, o1;
                o0.x = 0.5f*(c0 + b0)  + 0.5f*x0.x;
                o0.y = 0.5f*(c1 + b1v) + 0.5f*x0.y;
                o1.x = 0.5f*(c2 + b0)  + 0.5f*x1.x;
                o1.y = 0.5f*(c3 + b1v) + 0.5f*x1.y;
                *reinterpret_cast<float2*>(outF + (size_t)row*CDIM + col) = o0;
                *reinterpret_cast<float2*>(outF + (size_t)(row + 8)*CDIM + col) = o1;
            }
        }
    }
}

// ---------------- launch ----------------
extern "C" void kernel_launch(void* const* d_in, const int* in_sizes, int n_in,
                              void* d_out, int out_size) {
    const float* x    = (const float*)d_in[0];
    const float* ln_g = (const float*)d_in[1];
    const float* ln_b = (const float*)d_in[2];
    const float* Wd   = (const float*)d_in[3];
    const float* bd   = (const float*)d_in[4];
    const float* Wg   = (const float*)d_in[5];
    const float* bg   = (const float*)d_in[6];
    const float* dw_w = (const float*)d_in[7];
    const float* dw_b = (const float*)d_in[8];
    const float* W1   = (const float*)d_in[9];
    const float* b1   = (const float*)d_in[10];
    const float* W2   = (const float*)d_in[11];
    const float* b2   = (const float*)d_in[12];
    // d_in[13..16]: Wq, bq, Wk, bk — dead (softmax over 1 key == 1)
    const float* Wv   = (const float*)d_in[17];
    const float* bv   = (const float*)d_in[18];
    const float* Wo   = (const float*)d_in[19];
    const float* bo   = (const float*)d_in[20];
    const float* Wu   = (const float*)d_in[21];
    const float* bu   = (const float*)d_in[22];
    const float* Wld  = (const float*)d_in[23];
    const float* Wlu  = (const float*)d_in[24];
    float* out = (float*)d_out;

    cudaFuncSetAttribute(gemm_k<0>, cudaFuncAttributeMaxDynamicSharedMemorySize, SMEM_BYTES);
    cudaFuncSetAttribute(gemm_k<1>, cudaFuncAttributeMaxDynamicSharedMemorySize, SMEM_BYTES);
    cudaFuncSetAttribute(gemm_k<2>, cudaFuncAttributeMaxDynamicSharedMemorySize, SMEM_BYTES);
    cudaFuncSetAttribute(gemm_k<3>, cudaFuncAttributeMaxDynamicSharedMemorySize, SMEM_BYTES);

    // weight folding (parallel, coalesced)
    k_wvo <<<CHD/8, 256>>>(Wv, Wo);
    k_t1  <<<CHD, 512>>>(Wu, Wld);
    k_bue1<<<RNK, 256>>>(bu, Wld);
    k_w2t <<<CHD/8, 256>>>(W2);
    k_b12 <<<CHD, 128>>>(dw_b, W1, b1, bv, Wo, b2, bo, bd, bg, dw_w);
    k_wut <<<CDIM, 256>>>(Wu, Wlu);
    k_bue2<<<CDIM/256, 256>>>(bu, Wlu);
    k_wdg <<<NDGI, 256>>>(Wd, Wg, dw_w);
    k_w1t <<<CHD, 256>>>(W1);

    // main pipeline
    ln_k<<<BDIM, 256>>>(x, ln_g, ln_b);
    gemm_k<0><<<dim3(NDGI/128, BDIM/128), 256, SMEM_BYTES>>>(nullptr, nullptr);
    gemm_k<1><<<dim3(CHD/128,  BDIM/128), 256, SMEM_BYTES>>>(nullptr, nullptr);
    gemm_k<2><<<dim3(CHD/128,  BDIM/128), 256, SMEM_BYTES>>>(nullptr, nullptr);
    gemm_k<3><<<dim3(CDIM/128, BDIM/128), 256, SMEM_BYTES>>>(out, x);
}

// round 6
// speedup vs baseline: 2.3716x; 1.1021x over previous
#include <cuda_runtime.h>
#include <cuda_bf16.h>
#include <cstdint>

// Problem dims
#define BDIM 32768
#define CDIM 1024
#define CHD  256
#define NDGI 512   // interleaved d/g width
#define RNK  16

// ---------------- scratch (__device__ globals; no runtime alloc) ----------------
__device__ __nv_bfloat16 g_t [BDIM*CDIM];   // LN output, bf16
__device__ __nv_bfloat16 g_h [BDIM*CHD];    // after gate
__device__ __nv_bfloat16 g_gl[BDIM*CHD];    // after GELU
__device__ __nv_bfloat16 g_u [BDIM*CHD];    // after W2eff
__device__ __nv_bfloat16 g_Wdg[NDGI*CDIM];  // interleaved, transposed [512][1024]
__device__ __nv_bfloat16 g_W1t[CHD*CHD];    // [n][k]
__device__ __nv_bfloat16 g_W2t[CHD*CHD];    // W2eff transposed [n][k]
__device__ __nv_bfloat16 g_Wut[CDIM*CHD];   // Wu_eff transposed [1024][256]
__device__ float g_Wvo[CHD*CHD];
__device__ float g_t1 [CHD*RNK];
__device__ float g_tmpr[RNK];
__device__ float g_bdg[NDGI];
__device__ float g_b1e[CHD];
__device__ float g_b2e[CHD];
__device__ float g_bue[CDIM];

// ---------------- small helpers ----------------
__device__ __forceinline__ float sigm(float x) { return 1.f / (1.f + __expf(-x)); }
__device__ __forceinline__ float gelu_tanh(float x) {
    return 0.5f * x * (1.f + tanhf(0.7978845608028654f * (x + 0.044715f * x * x * x)));
}
__device__ __forceinline__ uint32_t smem_u32(const void* p) {
    return (uint32_t)__cvta_generic_to_shared(p);
}
__device__ __forceinline__ void cp16(uint32_t s, const void* g) {
    asm volatile("cp.async.cg.shared.global [%0], [%1], 16;\n" :: "r"(s), "l"(g));
}
__device__ __forceinline__ void cp_commit() { asm volatile("cp.async.commit_group;\n"); }
template <int N> __device__ __forceinline__ void cp_wait() {
    asm volatile("cp.async.wait_group %0;\n" :: "n"(N));
}

// ================= FOLD STAGE 1 : one launch, blockIdx-dispatched =================
// blocks [0,512)      : Wdg   (interleaved transpose of Wd/Wg)
// blocks [512,768)    : W1t   (transpose)
// blocks [768,832)    : Wvo = Wv @ Wo, 32x32 tiled fp32 GEMM
// blocks [832,1088)   : t1   = Wu @ Wld  (row reductions)
// blocks [1088,1104)  : tmpr[r] = bu . Wld[:,r]
// blocks [1104,1136)  : b1e, b2e-partial(bv.Wo + bo), bdg  (8 channels/block)
#define F1_GRID 1136
__global__ __launch_bounds__(256) void fold1(
        const float* __restrict__ Wd, const float* __restrict__ Wg,
        const float* __restrict__ dw_w, const float* __restrict__ dw_b,
        const float* __restrict__ W1, const float* __restrict__ b1,
        const float* __restrict__ Wv, const float* __restrict__ Wo,
        const float* __restrict__ Wu, const float* __restrict__ Wld,
        const float* __restrict__ bu, const float* __restrict__ bd,
        const float* __restrict__ bg, const float* __restrict__ bv,
        const float* __restrict__ bo) {
    const int b = blockIdx.x, tid = threadIdx.x;
    __shared__ float sm[2*32*33];   // 8.25 KB, reused by all tasks

    if (b < 512) {                  // ---- Wdg ----
        const int n = b, j = n >> 1;
        const bool isg = (n & 1);
        const float scale = isg ? 1.f : dw_w[j];
        const float* src = isg ? Wg : Wd;
        #pragma unroll
        for (int c = 0; c < 4; c++) {
            int k = c*256 + tid;
            g_Wdg[(size_t)n*CDIM + k] = __float2bfloat16(src[(size_t)k*CHD + j] * scale);
        }
    } else if (b < 768) {           // ---- W1t ----
        const int n = b - 512;
        g_W1t[n*CHD + tid] = __float2bfloat16(W1[tid*CHD + n]);
    } else if (b < 832) {           // ---- Wvo 32x32 tile GEMM ----
        const int bb = b - 768;
        const int i0 = (bb >> 3)*32, n0 = (bb & 7)*32;
        float (*sA)[33] = (float(*)[33])sm;
        float (*sB)[33] = (float(*)[33])(sm + 32*33);
        const int col = tid & 31, rg = tid >> 5;   // rg 0..7 -> rows rg*4..+3
        float acc[4] = {};
        for (int kc = 0; kc < 8; kc++) {
            int k0 = kc*32;
            for (int t = tid; t < 1024; t += 256) {
                int r = t >> 5, c = t & 31;
                sA[r][c] = Wv[(i0 + r)*CHD + k0 + c];
                sB[r][c] = Wo[(k0 + r)*CHD + n0 + c];
            }
            __syncthreads();
            #pragma unroll 8
            for (int kk = 0; kk < 32; kk++) {
                float bvv = sB[kk][col];
                #pragma unroll
                for (int q = 0; q < 4; q++) acc[q] += sA[rg*4 + q][kk] * bvv;
            }
            __syncthreads();
        }
        #pragma unroll
        for (int q = 0; q < 4; q++) g_Wvo[(i0 + rg*4 + q)*CHD + n0 + col] = acc[q];
    } else if (b < 1088) {          // ---- t1 rows ----
        const int i = b - 832;
        float* row = sm;
        #pragma unroll
        for (int c = 0; c < 4; c++) row[c*256 + tid] = Wu[(size_t)i*CDIM + c*256 + tid];
        __syncthreads();
        const int w = tid >> 5, lane = tid & 31;
        float s1 = 0.f, s2 = 0.f;
        for (int j = lane; j < CDIM; j += 32) {
            float rj = row[j];
            s1 += rj * Wld[j*RNK + w];
            s2 += rj * Wld[j*RNK + w + 8];
        }
        #pragma unroll
        for (int o = 16; o; o >>= 1) {
            s1 += __shfl_xor_sync(~0u, s1, o);
            s2 += __shfl_xor_sync(~0u, s2, o);
        }
        if (lane == 0) { g_t1[i*RNK + w] = s1; g_t1[i*RNK + w + 8] = s2; }
    } else if (b < 1104) {          // ---- tmpr ----
        const int r = b - 1088;
        float s = 0.f;
        for (int j = tid; j < CDIM; j += 256) s += bu[j] * Wld[j*RNK + r];
        #pragma unroll
        for (int o = 16; o; o >>= 1) s += __shfl_xor_sync(~0u, s, o);
        if ((tid & 31) == 0) sm[tid >> 5] = s;
        __syncthreads();
        if (tid == 0) {
            float S = 0.f;
            #pragma unroll
            for (int q = 0; q < 8; q++) S += sm[q];
            g_tmpr[r] = S;
        }
    } else {                        // ---- b1e / b2e-part / bdg ----
        const int w = tid >> 5, lane = tid & 31;
        const int t = (b - 1104)*8 + w;
        float s1 = 0.f, s2 = 0.f;
        for (int k = lane; k < CHD; k += 32) {
            s1 += dw_b[k] * W1[k*CHD + t];
            s2 += bv[k]  * Wo[k*CHD + t];
        }
        #pragma unroll
        for (int o = 16; o; o >>= 1) {
            s1 += __shfl_xor_sync(~0u, s1, o);
            s2 += __shfl_xor_sync(~0u, s2, o);
        }
        if (lane == 0) {
            g_b1e[t] = b1[t] + s1;
            g_b2e[t] = s2 + bo[t];        // partial; fold2 adds b2.Wvo
            g_bdg[2*t]     = bd[t] * dw_w[t];
            g_bdg[2*t + 1] = bg[t];
        }
    }
}

// ================= FOLD STAGE 2 =================
// blocks [0,64)       : W2t = (W2 @ Wvo)^T, 32x32 tiled GEMM, bf16 out
// blocks [64,1088)    : Wut rows (needs t1)
// blocks [1088,1092)  : bue (needs tmpr)
// blocks [1092,1124)  : b2e += b2 . Wvo
#define F2_GRID 1124
__global__ __launch_bounds__(256) void fold2(
        const float* __restrict__ W2, const float* __restrict__ Wu,
        const float* __restrict__ Wlu, const float* __restrict__ bu,
        const float* __restrict__ b2) {
    const int b = blockIdx.x, tid = threadIdx.x;
    __shared__ float sm[2*32*33];

    if (b < 64) {                   // ---- W2t tile GEMM ----
        const int i0 = (b >> 3)*32, n0 = (b & 7)*32;
        float (*sA)[33] = (float(*)[33])sm;
        float (*sB)[33] = (float(*)[33])(sm + 32*33);
        const int col = tid & 31, rg = tid >> 5;
        float acc[4] = {};
        for (int kc = 0; kc < 8; kc++) {
            int k0 = kc*32;
            for (int t = tid; t < 1024; t += 256) {
                int r = t >> 5, c = t & 31;
                sA[r][c] = W2[(i0 + r)*CHD + k0 + c];
                sB[r][c] = g_Wvo[(k0 + r)*CHD + n0 + c];
            }
            __syncthreads();
            #pragma unroll 8
            for (int kk = 0; kk < 32; kk++) {
                float bvv = sB[kk][col];
                #pragma unroll
                for (int q = 0; q < 4; q++) acc[q] += sA[rg*4 + q][kk] * bvv;
            }
            __syncthreads();
        }
        #pragma unroll
        for (int q = 0; q < 4; q++)
            g_W2t[(n0 + col)*CHD + i0 + rg*4 + q] = __float2bfloat16(acc[q]);
    } else if (b < 1088) {          // ---- Wut rows ----
        const int n = b - 64, i = tid;
        float v = Wu[(size_t)i*CDIM + n];
        const float* t1r = &g_t1[i*RNK];
        #pragma unroll
        for (int r = 0; r < RNK; r++) v += t1r[r] * Wlu[r*CDIM + n];
        g_Wut[(size_t)n*CHD + i] = __float2bfloat16(v);
    } else if (b < 1092) {          // ---- bue ----
        const int n = (b - 1088)*256 + tid;
        float v = bu[n];
        #pragma unroll
        for (int r = 0; r < RNK; r++) v += g_tmpr[r] * Wlu[r*CDIM + n];
        g_bue[n] = v;
    } else {                        // ---- b2e += b2 . Wvo ----
        const int w = tid >> 5, lane = tid & 31;
        const int t = (b - 1092)*8 + w;
        float s = 0.f;
        for (int m = lane; m < CHD; m += 32) s += b2[m] * g_Wvo[m*CHD + t];
        #pragma unroll
        for (int o = 16; o; o >>= 1) s += __shfl_xor_sync(~0u, s, o);
        if (lane == 0) g_b2e[t] += s;
    }
}

// ---------------- LayerNorm -> bf16 ----------------
__global__ __launch_bounds__(256) void ln_k(const float* __restrict__ x,
                                            const float* __restrict__ lg,
                                            const float* __restrict__ lb) {
    int row = blockIdx.x, tid = threadIdx.x;
    const float4 v = reinterpret_cast<const float4*>(x)[(size_t)row*256 + tid];
    float s = v.x + v.y + v.z + v.w;
    float q = v.x*v.x + v.y*v.y + v.z*v.z + v.w*v.w;
    #pragma unroll
    for (int o = 16; o; o >>= 1) {
        s += __shfl_xor_sync(~0u, s, o);
        q += __shfl_xor_sync(~0u, q, o);
    }
    __shared__ float rs[8], rq[8], stats[2];
    int w = tid >> 5;
    if ((tid & 31) == 0) { rs[w] = s; rq[w] = q; }
    __syncthreads();
    if (tid == 0) {
        float S = 0.f, Q = 0.f;
        #pragma unroll
        for (int i = 0; i < 8; i++) { S += rs[i]; Q += rq[i]; }
        float mu = S * (1.f/1024.f);
        float var = Q * (1.f/1024.f) - mu*mu;
        stats[0] = mu; stats[1] = rsqrtf(var + 1e-5f);
    }
    __syncthreads();
    float mu = stats[0], rstd = stats[1];
    const float4 g4 = reinterpret_cast<const float4*>(lg)[tid];
    const float4 b4 = reinterpret_cast<const float4*>(lb)[tid];
    float t0 = (v.x-mu)*rstd*g4.x + b4.x;
    float t1 = (v.y-mu)*rstd*g4.y + b4.y;
    float t2 = (v.z-mu)*rstd*g4.z + b4.z;
    float t3 = (v.w-mu)*rstd*g4.w + b4.w;
    __nv_bfloat162 p0, p1;
    p0.x = __float2bfloat16(t0); p0.y = __float2bfloat16(t1);
    p1.x = __float2bfloat16(t2); p1.y = __float2bfloat16(t3);
    __nv_bfloat162* dst = reinterpret_cast<__nv_bfloat162*>(g_t + (size_t)row*CDIM);
    dst[2*tid]   = p0;
    dst[2*tid+1] = p1;
}

// ---------------- mma.sync bf16 GEMM, 128x128 tile, 3-stage, 1 sync/iter ----------------
#define STG_A (128*40)
#define STG_B (128*40)
#define SMEM_BYTES (3*(STG_A + STG_B)*2)

template <int SEL>
__global__ __launch_bounds__(256) void gemm_k(float* __restrict__ outF,
                                              const float* __restrict__ xres) {
    constexpr int K = (SEL == 0) ? CDIM : CHD;
    const __nv_bfloat16* A  = (SEL==0) ? g_t   : (SEL==1) ? g_h   : (SEL==2) ? g_gl : g_u;
    const __nv_bfloat16* Bm = (SEL==0) ? g_Wdg : (SEL==1) ? g_W1t : (SEL==2) ? g_W2t : g_Wut;
    const float* bias       = (SEL==0) ? g_bdg : (SEL==1) ? g_b1e : (SEL==2) ? g_b2e : g_bue;

    extern __shared__ __align__(16) __nv_bfloat16 smem[];
    __nv_bfloat16* Abase = smem;
    __nv_bfloat16* Bbase = smem + 3*STG_A;

    const int tid = threadIdx.x;
    const int lane = tid & 31, warp = tid >> 5;
    const int wm = warp >> 1, wn = warp & 1;
    const int m0 = blockIdx.y * 128, n0 = blockIdx.x * 128;

    const int lrow = tid >> 2, lkc = tid & 3;
    const __nv_bfloat16* Ag  = A  + (size_t)(m0 + lrow)      * K + lkc*8;
    const __nv_bfloat16* Ag2 = A  + (size_t)(m0 + lrow + 64) * K + lkc*8;
    const __nv_bfloat16* Bg  = Bm + (size_t)(n0 + lrow)      * K + lkc*8;
    const __nv_bfloat16* Bg2 = Bm + (size_t)(n0 + lrow + 64) * K + lkc*8;
    const uint32_t sA  = smem_u32(Abase + lrow*40 + lkc*8);
    const uint32_t sA2 = smem_u32(Abase + (lrow + 64)*40 + lkc*8);
    const uint32_t sB  = smem_u32(Bbase + lrow*40 + lkc*8);
    const uint32_t sB2 = smem_u32(Bbase + (lrow + 64)*40 + lkc*8);
    const uint32_t stS = STG_A*2;

    float acc[2][8][4] = {};
    constexpr int KT = K / 32;

    cp16(sA, Ag); cp16(sA2, Ag2); cp16(sB, Bg); cp16(sB2, Bg2);
    cp_commit();
    cp16(sA + stS, Ag + 32); cp16(sA2 + stS, Ag2 + 32);
    cp16(sB + stS, Bg + 32); cp16(sB2 + stS, Bg2 + 32);
    cp_commit();

    int buf = 0;
    for (int kt = 0; kt < KT; kt++) {
        if (kt == KT - 1) cp_wait<0>(); else cp_wait<1>();
        __syncthreads();
        if (kt + 2 < KT) {
            int wb = (buf + 2 >= 3) ? buf - 1 : buf + 2;
            cp16(sA  + wb*stS, Ag  + (kt+2)*32);
            cp16(sA2 + wb*stS, Ag2 + (kt+2)*32);
            cp16(sB  + wb*stS, Bg  + (kt+2)*32);
            cp16(sB2 + wb*stS, Bg2 + (kt+2)*32);
            cp_commit();
        }
        const __nv_bfloat16* Asb = Abase + buf*STG_A;
        const __nv_bfloat16* Bsb = Bbase + buf*STG_B;
        #pragma unroll
        for (int ks = 0; ks < 2; ks++) {
            uint32_t a[2][4], b[8][2];
            #pragma unroll
            for (int i = 0; i < 2; i++) {
                const __nv_bfloat16* p = Asb + (wm*32 + i*16 + (lane & 15))*40 + ks*16 + (lane >> 4)*8;
                asm volatile("ldmatrix.sync.aligned.m8n8.x4.shared.b16 {%0,%1,%2,%3},[%4];"
                             : "=r"(a[i][0]), "=r"(a[i][1]), "=r"(a[i][2]), "=r"(a[i][3])
                             : "r"(smem_u32(p)));
            }
            #pragma unroll
            for (int j = 0; j < 8; j++) {
                const __nv_bfloat16* p = Bsb + (wn*64 + j*8 + (lane & 7))*40 + ks*16 + ((lane >> 3) & 1)*8;
                asm volatile("ldmatrix.sync.aligned.m8n8.x2.shared.b16 {%0,%1},[%2];"
                             : "=r"(b[j][0]), "=r"(b[j][1]) : "r"(smem_u32(p)));
            }
            #pragma unroll
            for (int i = 0; i < 2; i++)
                #pragma unroll
                for (int j = 0; j < 8; j++)
                    asm volatile("mma.sync.aligned.m16n8k16.row.col.f32.bf16.bf16.f32 "
                                 "{%0,%1,%2,%3},{%4,%5,%6,%7},{%8,%9},{%0,%1,%2,%3};"
                                 : "+f"(acc[i][j][0]), "+f"(acc[i][j][1]),
                                   "+f"(acc[i][j][2]), "+f"(acc[i][j][3])
                                 : "r"(a[i][0]), "r"(a[i][1]), "r"(a[i][2]), "r"(a[i][3]),
                                   "r"(b[j][0]), "r"(b[j][1]));
        }
        buf = (buf + 1 >= 3) ? 0 : buf + 1;
    }

    #pragma unroll
    for (int i = 0; i < 2; i++) {
        #pragma unroll
        for (int j = 0; j < 8; j++) {
            int row = m0 + wm*32 + i*16 + (lane >> 2);
            int col = n0 + wn*64 + j*8 + (lane & 3)*2;
            float c0 = acc[i][j][0], c1 = acc[i][j][1];
            float c2 = acc[i][j][2], c3 = acc[i][j][3];
            if (SEL == 0) {
                float bdv = bias[col], bgv = bias[col + 1];
                float h0 = (c0 + bdv) * sigm(c1 + bgv);
                float h1 = (c2 + bdv) * sigm(c3 + bgv);
                g_h[(size_t)row*CHD + (col >> 1)]       = __float2bfloat16(h0);
                g_h[(size_t)(row + 8)*CHD + (col >> 1)] = __float2bfloat16(h1);
            } else if (SEL == 1 || SEL == 2) {
                float b0 = bias[col], b1v = bias[col + 1];
                float v0 = c0 + b0, v1 = c1 + b1v, v2 = c2 + b0, v3 = c3 + b1v;
                if (SEL == 1) {
                    v0 = gelu_tanh(v0); v1 = gelu_tanh(v1);
                    v2 = gelu_tanh(v2); v3 = gelu_tanh(v3);
                }
                __nv_bfloat16* dst = (SEL == 1) ? g_gl : g_u;
                __nv_bfloat162 p0, p1;
                p0.x = __float2bfloat16(v0); p0.y = __float2bfloat16(v1);
                p1.x = __float2bfloat16(v2); p1.y = __float2bfloat16(v3);
                *reinterpret_cast<__nv_bfloat162*>(dst + (size_t)row*CHD + col) = p0;
                *reinterpret_cast<__nv_bfloat162*>(dst + (size_t)(row + 8)*CHD + col) = p1;
            } else {
                float b0 = bias[col], b1v = bias[col + 1];
                const float2 x0 = *reinterpret_cast<const float2*>(xres + (size_t)row*CDIM + col);
                const float2 x1 = *reinterpret_cast<const float2*>(xres + (size_t)(row + 8)*CDIM + col);
                float2 o0, o1;
                o0.x = 0.5f*(c0 + b0)  + 0.5f*x0.x;
                o0.y = 0.5f*(c1 + b1v) + 0.5f*x0.y;
                o1.x = 0.5f*(c2 + b0)  + 0.5f*x1.x;
                o1.y = 0.5f*(c3 + b1v) + 0.5f*x1.y;
                *reinterpret_cast<float2*>(outF + (size_t)row*CDIM + col) = o0;
                *reinterpret_cast<float2*>(outF + (size_t)(row + 8)*CDIM + col) = o1;
            }
        }
    }
}

// ---------------- launch ----------------
extern "C" void kernel_launch(void* const* d_in, const int* in_sizes, int n_in,
                              void* d_out, int out_size) {
    const float* x    = (const float*)d_in[0];
    const float* ln_g = (const float*)d_in[1];
    const float* ln_b = (const float*)d_in[2];
    const float* Wd   = (const float*)d_in[3];
    const float* bd   = (const float*)d_in[4];
    const float* Wg   = (const float*)d_in[5];
    const float* bg   = (const float*)d_in[6];
    const float* dw_w = (const float*)d_in[7];
    const float* dw_b = (const float*)d_in[8];
    const float* W1   = (const float*)d_in[9];
    const float* b1   = (const float*)d_in[10];
    const float* W2   = (const float*)d_in[11];
    const float* b2   = (const float*)d_in[12];
    // d_in[13..16]: Wq, bq, Wk, bk — dead (softmax over 1 key == 1)
    const float* Wv   = (const float*)d_in[17];
    const float* bv   = (const float*)d_in[18];
    const float* Wo   = (const float*)d_in[19];
    const float* bo   = (const float*)d_in[20];
    const float* Wu   = (const float*)d_in[21];
    const float* bu   = (const float*)d_in[22];
    const float* Wld  = (const float*)d_in[23];
    const float* Wlu  = (const float*)d_in[24];
    float* out = (float*)d_out;

    cudaFuncSetAttribute(gemm_k<0>, cudaFuncAttributeMaxDynamicSharedMemorySize, SMEM_BYTES);
    cudaFuncSetAttribute(gemm_k<1>, cudaFuncAttributeMaxDynamicSharedMemorySize, SMEM_BYTES);
    cudaFuncSetAttribute(gemm_k<2>, cudaFuncAttributeMaxDynamicSharedMemorySize, SMEM_BYTES);
    cudaFuncSetAttribute(gemm_k<3>, cudaFuncAttributeMaxDynamicSharedMemorySize, SMEM_BYTES);

    // weight folding: 2 chip-filling launches
    fold1<<<F1_GRID, 256>>>(Wd, Wg, dw_w, dw_b, W1, b1, Wv, Wo, Wu, Wld, bu, bd, bg, bv, bo);
    fold2<<<F2_GRID, 256>>>(W2, Wu, Wlu, bu, b2);

    // main pipeline
    ln_k<<<BDIM, 256>>>(x, ln_g, ln_b);
    gemm_k<0><<<dim3(NDGI/128, BDIM/128), 256, SMEM_BYTES>>>(nullptr, nullptr);
    gemm_k<1><<<dim3(CHD/128,  BDIM/128), 256, SMEM_BYTES>>>(nullptr, nullptr);
    gemm_k<2><<<dim3(CHD/128,  BDIM/128), 256, SMEM_BYTES>>>(nullptr, nullptr);
    gemm_k<3><<<dim3(CDIM/128, BDIM/128), 256, SMEM_BYTES>>>(out, x);
}

// round 13
// speedup vs baseline: 2.4669x; 1.0402x over previous
#include <cuda_runtime.h>
#include <cuda_bf16.h>
#include <cstdint>

// Problem dims
#define BDIM 32768
#define CDIM 1024
#define CHD  256
#define NDGI 512
#define RNK  16

// ---------------- scratch ----------------
__device__ __nv_bfloat16 g_t [BDIM*CDIM];
__device__ __nv_bfloat16 g_h [BDIM*CHD];
__device__ __nv_bfloat16 g_gl[BDIM*CHD];
__device__ __nv_bfloat16 g_u [BDIM*CHD];
__device__ __nv_bfloat16 g_Wdg[NDGI*CDIM];
__device__ __nv_bfloat16 g_W1t[CHD*CHD];
__device__ __nv_bfloat16 g_W2t[CHD*CHD];
__device__ __nv_bfloat16 g_Wut[CDIM*CHD];
__device__ float g_Wvo[CHD*CHD];
__device__ float g_t1 [CHD*RNK];
__device__ float g_tmpr[RNK];
__device__ float g_bdg[NDGI];
__device__ float g_b1e[CHD];
__device__ float g_b2e[CHD];
__device__ float g_bue[CDIM];

// ---------------- helpers ----------------
__device__ __forceinline__ float sigm(float x) { return 1.f / (1.f + __expf(-x)); }
__device__ __forceinline__ float gelu_tanh(float x) {
    return 0.5f * x * (1.f + tanhf(0.7978845608028654f * (x + 0.044715f * x * x * x)));
}
__device__ __forceinline__ uint32_t smem_u32(const void* p) {
    return (uint32_t)__cvta_generic_to_shared(p);
}
__device__ __forceinline__ void cp16(uint32_t s, const void* g) {
    asm volatile("cp.async.cg.shared.global [%0], [%1], 16;\n" :: "r"(s), "l"(g));
}
__device__ __forceinline__ void cp_commit() { asm volatile("cp.async.commit_group;\n"); }
template <int N> __device__ __forceinline__ void cp_wait() {
    asm volatile("cp.async.wait_group %0;\n" :: "n"(N));
}

// ================= FOLD STAGE 1 =================
#define F1_GRID 1136
__global__ __launch_bounds__(256) void fold1(
        const float* __restrict__ Wd, const float* __restrict__ Wg,
        const float* __restrict__ dw_w, const float* __restrict__ dw_b,
        const float* __restrict__ W1, const float* __restrict__ b1,
        const float* __restrict__ Wv, const float* __restrict__ Wo,
        const float* __restrict__ Wu, const float* __restrict__ Wld,
        const float* __restrict__ bu, const float* __restrict__ bd,
        const float* __restrict__ bg, const float* __restrict__ bv,
        const float* __restrict__ bo) {
    const int b = blockIdx.x, tid = threadIdx.x;
    __shared__ float sm[2*32*33];

    if (b < 512) {
        const int n = b, j = n >> 1;
        const bool isg = (n & 1);
        const float scale = isg ? 1.f : dw_w[j];
        const float* src = isg ? Wg : Wd;
        #pragma unroll
        for (int c = 0; c < 4; c++) {
            int k = c*256 + tid;
            g_Wdg[(size_t)n*CDIM + k] = __float2bfloat16(src[(size_t)k*CHD + j] * scale);
        }
    } else if (b < 768) {
        const int n = b - 512;
        g_W1t[n*CHD + tid] = __float2bfloat16(W1[tid*CHD + n]);
    } else if (b < 832) {
        const int bb = b - 768;
        const int i0 = (bb >> 3)*32, n0 = (bb & 7)*32;
        float (*sA)[33] = (float(*)[33])sm;
        float (*sB)[33] = (float(*)[33])(sm + 32*33);
        const int col = tid & 31, rg = tid >> 5;
        float acc[4] = {};
        for (int kc = 0; kc < 8; kc++) {
            int k0 = kc*32;
            for (int t = tid; t < 1024; t += 256) {
                int r = t >> 5, c = t & 31;
                sA[r][c] = Wv[(i0 + r)*CHD + k0 + c];
                sB[r][c] = Wo[(k0 + r)*CHD + n0 + c];
            }
            __syncthreads();
            #pragma unroll 8
            for (int kk = 0; kk < 32; kk++) {
                float bvv = sB[kk][col];
                #pragma unroll
                for (int q = 0; q < 4; q++) acc[q] += sA[rg*4 + q][kk] * bvv;
            }
            __syncthreads();
        }
        #pragma unroll
        for (int q = 0; q < 4; q++) g_Wvo[(i0 + rg*4 + q)*CHD + n0 + col] = acc[q];
    } else if (b < 1088) {
        const int i = b - 832;
        float* row = sm;
        #pragma unroll
        for (int c = 0; c < 4; c++) row[c*256 + tid] = Wu[(size_t)i*CDIM + c*256 + tid];
        __syncthreads();
        const int w = tid >> 5, lane = tid & 31;
        float s1 = 0.f, s2 = 0.f;
        for (int j = lane; j < CDIM; j += 32) {
            float rj = row[j];
            s1 += rj * Wld[j*RNK + w];
            s2 += rj * Wld[j*RNK + w + 8];
        }
        #pragma unroll
        for (int o = 16; o; o >>= 1) {
            s1 += __shfl_xor_sync(~0u, s1, o);
            s2 += __shfl_xor_sync(~0u, s2, o);
        }
        if (lane == 0) { g_t1[i*RNK + w] = s1; g_t1[i*RNK + w + 8] = s2; }
    } else if (b < 1104) {
        const int r = b - 1088;
        float s = 0.f;
        for (int j = tid; j < CDIM; j += 256) s += bu[j] * Wld[j*RNK + r];
        #pragma unroll
        for (int o = 16; o; o >>= 1) s += __shfl_xor_sync(~0u, s, o);
        if ((tid & 31) == 0) sm[tid >> 5] = s;
        __syncthreads();
        if (tid == 0) {
            float S = 0.f;
            #pragma unroll
            for (int q = 0; q < 8; q++) S += sm[q];
            g_tmpr[r] = S;
        }
    } else {
        const int w = tid >> 5, lane = tid & 31;
        const int t = (b - 1104)*8 + w;
        float s1 = 0.f, s2 = 0.f;
        for (int k = lane; k < CHD; k += 32) {
            s1 += dw_b[k] * W1[k*CHD + t];
            s2 += bv[k]  * Wo[k*CHD + t];
        }
        #pragma unroll
        for (int o = 16; o; o >>= 1) {
            s1 += __shfl_xor_sync(~0u, s1, o);
            s2 += __shfl_xor_sync(~0u, s2, o);
        }
        if (lane == 0) {
            g_b1e[t] = b1[t] + s1;
            g_b2e[t] = s2 + bo[t];
            g_bdg[2*t]     = bd[t] * dw_w[t];
            g_bdg[2*t + 1] = bg[t];
        }
    }
}

// ================= FOLD STAGE 2 =================
#define F2_GRID 1124
__global__ __launch_bounds__(256) void fold2(
        const float* __restrict__ W2, const float* __restrict__ Wu,
        const float* __restrict__ Wlu, const float* __restrict__ bu,
        const float* __restrict__ b2) {
    const int b = blockIdx.x, tid = threadIdx.x;
    __shared__ float sm[2*32*33];

    if (b < 64) {
        const int i0 = (b >> 3)*32, n0 = (b & 7)*32;
        float (*sA)[33] = (float(*)[33])sm;
        float (*sB)[33] = (float(*)[33])(sm + 32*33);
        const int col = tid & 31, rg = tid >> 5;
        float acc[4] = {};
        for (int kc = 0; kc < 8; kc++) {
            int k0 = kc*32;
            for (int t = tid; t < 1024; t += 256) {
                int r = t >> 5, c = t & 31;
                sA[r][c] = W2[(i0 + r)*CHD + k0 + c];
                sB[r][c] = g_Wvo[(k0 + r)*CHD + n0 + c];
            }
            __syncthreads();
            #pragma unroll 8
            for (int kk = 0; kk < 32; kk++) {
                float bvv = sB[kk][col];
                #pragma unroll
                for (int q = 0; q < 4; q++) acc[q] += sA[rg*4 + q][kk] * bvv;
            }
            __syncthreads();
        }
        #pragma unroll
        for (int q = 0; q < 4; q++)
            g_W2t[(n0 + col)*CHD + i0 + rg*4 + q] = __float2bfloat16(acc[q]);
    } else if (b < 1088) {
        const int n = b - 64, i = tid;
        float v = Wu[(size_t)i*CDIM + n];
        const float* t1r = &g_t1[i*RNK];
        #pragma unroll
        for (int r = 0; r < RNK; r++) v += t1r[r] * Wlu[r*CDIM + n];
        g_Wut[(size_t)n*CHD + i] = __float2bfloat16(v);
    } else if (b < 1092) {
        const int n = (b - 1088)*256 + tid;
        float v = bu[n];
        #pragma unroll
        for (int r = 0; r < RNK; r++) v += g_tmpr[r] * Wlu[r*CDIM + n];
        g_bue[n] = v;
    } else {
        const int w = tid >> 5, lane = tid & 31;
        const int t = (b - 1092)*8 + w;
        float s = 0.f;
        for (int m = lane; m < CHD; m += 32) s += b2[m] * g_Wvo[m*CHD + t];
        #pragma unroll
        for (int o = 16; o; o >>= 1) s += __shfl_xor_sync(~0u, s, o);
        if (lane == 0) g_b2e[t] += s;
    }
}

// ---------------- LayerNorm -> bf16 ----------------
__global__ __launch_bounds__(256) void ln_k(const float* __restrict__ x,
                                            const float* __restrict__ lg,
                                            const float* __restrict__ lb) {
    int row = blockIdx.x, tid = threadIdx.x;
    const float4 v = reinterpret_cast<const float4*>(x)[(size_t)row*256 + tid];
    float s = v.x + v.y + v.z + v.w;
    float q = v.x*v.x + v.y*v.y + v.z*v.z + v.w*v.w;
    #pragma unroll
    for (int o = 16; o; o >>= 1) {
        s += __shfl_xor_sync(~0u, s, o);
        q += __shfl_xor_sync(~0u, q, o);
    }
    __shared__ float rs[8], rq[8], stats[2];
    int w = tid >> 5;
    if ((tid & 31) == 0) { rs[w] = s; rq[w] = q; }
    __syncthreads();
    if (tid == 0) {
        float S = 0.f, Q = 0.f;
        #pragma unroll
        for (int i = 0; i < 8; i++) { S += rs[i]; Q += rq[i]; }
        float mu = S * (1.f/1024.f);
        float var = Q * (1.f/1024.f) - mu*mu;
        stats[0] = mu; stats[1] = rsqrtf(var + 1e-5f);
    }
    __syncthreads();
    float mu = stats[0], rstd = stats[1];
    const float4 g4 = reinterpret_cast<const float4*>(lg)[tid];
    const float4 b4 = reinterpret_cast<const float4*>(lb)[tid];
    float t0 = (v.x-mu)*rstd*g4.x + b4.x;
    float t1 = (v.y-mu)*rstd*g4.y + b4.y;
    float t2 = (v.z-mu)*rstd*g4.z + b4.z;
    float t3 = (v.w-mu)*rstd*g4.w + b4.w;
    __nv_bfloat162 p0, p1;
    p0.x = __float2bfloat16(t0); p0.y = __float2bfloat16(t1);
    p1.x = __float2bfloat16(t2); p1.y = __float2bfloat16(t3);
    __nv_bfloat162* dst = reinterpret_cast<__nv_bfloat162*>(g_t + (size_t)row*CDIM);
    dst[2*tid]   = p0;
    dst[2*tid+1] = p1;
}

// ======== mma.sync bf16 GEMM, 128x128 tile, K-chunk 64, 3-stage, 1 sync/iter ========
#define LDROW 72                 // padded row stride (elements) for 64-wide chunk
#define STG_E (128*LDROW)        // elements per matrix per stage
#define SMEM_BYTES (3*2*STG_E*2) // 3 stages x (A+B) x bf16

template <int SEL>
__global__ __launch_bounds__(256) void gemm_k(float* __restrict__ outF,
                                              const float* __restrict__ xres) {
    constexpr int K = (SEL == 0) ? CDIM : CHD;
    constexpr int KT = K / 64;
    const __nv_bfloat16* A  = (SEL==0) ? g_t   : (SEL==1) ? g_h   : (SEL==2) ? g_gl : g_u;
    const __nv_bfloat16* Bm = (SEL==0) ? g_Wdg : (SEL==1) ? g_W1t : (SEL==2) ? g_W2t : g_Wut;
    const float* bias       = (SEL==0) ? g_bdg : (SEL==1) ? g_b1e : (SEL==2) ? g_b2e : g_bue;

    extern __shared__ __align__(16) __nv_bfloat16 smem[];
    __nv_bfloat16* Abase = smem;                // 3 stages of [128][72]
    __nv_bfloat16* Bbase = smem + 3*STG_E;

    const int tid = threadIdx.x;
    const int lane = tid & 31, warp = tid >> 5;
    const int wm = warp >> 1, wn = warp & 1;
    const int m0 = blockIdx.y * 128, n0 = blockIdx.x * 128;

    // loader: 1024 16B-chunks per matrix per stage; thread t does chunks t, t+256, ...
    // chunk c: row = c>>3, col16 = c&7
    uint32_t sAo[4], sBo[4];
    const __nv_bfloat16 *gA[4], *gB[4];
    #pragma unroll
    for (int q = 0; q < 4; q++) {
        int c = tid + q*256;
        int row = c >> 3, c16 = c & 7;
        sAo[q] = (uint32_t)(row*LDROW + c16*8)*2;
        sBo[q] = sAo[q];
        gA[q] = A  + (size_t)(m0 + row)*K + c16*8;
        gB[q] = Bm + (size_t)(n0 + row)*K + c16*8;
    }
    const uint32_t sAb = smem_u32(Abase), sBb = smem_u32(Bbase);
    const uint32_t stS = STG_E*2;   // bytes per stage

    float acc[2][8][4] = {};

    // prologue: stages 0,1
    #pragma unroll
    for (int q = 0; q < 4; q++) { cp16(sAb + sAo[q], gA[q]); cp16(sBb + sBo[q], gB[q]); }
    cp_commit();
    if (KT > 1) {
        #pragma unroll
        for (int q = 0; q < 4; q++) {
            cp16(sAb + stS + sAo[q], gA[q] + 64);
            cp16(sBb + stS + sBo[q], gB[q] + 64);
        }
        cp_commit();
    }

    int buf = 0;
    for (int kt = 0; kt < KT; kt++) {
        if (kt == KT - 1) cp_wait<0>(); else cp_wait<1>();
        __syncthreads();
        if (kt + 2 < KT) {
            int wb = (buf + 2 >= 3) ? buf - 1 : buf + 2;
            #pragma unroll
            for (int q = 0; q < 4; q++) {
                cp16(sAb + wb*stS + sAo[q], gA[q] + (kt+2)*64);
                cp16(sBb + wb*stS + sBo[q], gB[q] + (kt+2)*64);
            }
            cp_commit();
        }
        const __nv_bfloat16* Asb = Abase + buf*STG_E;
        const __nv_bfloat16* Bsb = Bbase + buf*STG_E;
        #pragma unroll
        for (int ks = 0; ks < 4; ks++) {
            uint32_t a[2][4], b[4][4];
            #pragma unroll
            for (int i = 0; i < 2; i++) {
                const __nv_bfloat16* p = Asb + (wm*32 + i*16 + (lane & 15))*LDROW
                                             + ks*16 + (lane >> 4)*8;
                asm volatile("ldmatrix.sync.aligned.m8n8.x4.shared.b16 {%0,%1,%2,%3},[%4];"
                             : "=r"(a[i][0]), "=r"(a[i][1]), "=r"(a[i][2]), "=r"(a[i][3])
                             : "r"(smem_u32(p)));
            }
            #pragma unroll
            for (int j2 = 0; j2 < 4; j2++) {
                const __nv_bfloat16* p = Bsb + (wn*64 + j2*16 + (lane >> 4)*8 + (lane & 7))*LDROW
                                             + ks*16 + ((lane >> 3) & 1)*8;
                asm volatile("ldmatrix.sync.aligned.m8n8.x4.shared.b16 {%0,%1,%2,%3},[%4];"
                             : "=r"(b[j2][0]), "=r"(b[j2][1]), "=r"(b[j2][2]), "=r"(b[j2][3])
                             : "r"(smem_u32(p)));
            }
            #pragma unroll
            for (int i = 0; i < 2; i++)
                #pragma unroll
                for (int j2 = 0; j2 < 4; j2++) {
                    asm volatile("mma.sync.aligned.m16n8k16.row.col.f32.bf16.bf16.f32 "
                                 "{%0,%1,%2,%3},{%4,%5,%6,%7},{%8,%9},{%0,%1,%2,%3};"
                                 : "+f"(acc[i][2*j2][0]), "+f"(acc[i][2*j2][1]),
                                   "+f"(acc[i][2*j2][2]), "+f"(acc[i][2*j2][3])
                                 : "r"(a[i][0]), "r"(a[i][1]), "r"(a[i][2]), "r"(a[i][3]),
                                   "r"(b[j2][0]), "r"(b[j2][1]));
                    asm volatile("mma.sync.aligned.m16n8k16.row.col.f32.bf16.bf16.f32 "
                                 "{%0,%1,%2,%3},{%4,%5,%6,%7},{%8,%9},{%0,%1,%2,%3};"
                                 : "+f"(acc[i][2*j2+1][0]), "+f"(acc[i][2*j2+1][1]),
                                   "+f"(acc[i][2*j2+1][2]), "+f"(acc[i][2*j2+1][3])
                                 : "r"(a[i][0]), "r"(a[i][1]), "r"(a[i][2]), "r"(a[i][3]),
                                   "r"(b[j2][2]), "r"(b[j2][3]));
                }
        }
        buf = (buf + 1 >= 3) ? 0 : buf + 1;
    }

    // epilogue (same mapping as R6)
    #pragma unroll
    for (int i = 0; i < 2; i++) {
        #pragma unroll
        for (int j = 0; j < 8; j++) {
            int row = m0 + wm*32 + i*16 + (lane >> 2);
            int col = n0 + wn*64 + j*8 + (lane & 3)*2;
            float c0 = acc[i][j][0], c1 = acc[i][j][1];
            float c2 = acc[i][j][2], c3 = acc[i][j][3];
            if (SEL == 0) {
                float bdv = bias[col], bgv = bias[col + 1];
                float h0 = (c0 + bdv) * sigm(c1 + bgv);
                float h1 = (c2 + bdv) * sigm(c3 + bgv);
                g_h[(size_t)row*CHD + (col >> 1)]       = __float2bfloat16(h0);
                g_h[(size_t)(row + 8)*CHD + (col >> 1)] = __float2bfloat16(h1);
            } else if (SEL == 1 || SEL == 2) {
                float b0 = bias[col], b1v = bias[col + 1];
                float v0 = c0 + b0, v1 = c1 + b1v, v2 = c2 + b0, v3 = c3 + b1v;
                if (SEL == 1) {
                    v0 = gelu_tanh(v0); v1 = gelu_tanh(v1);
                    v2 = gelu_tanh(v2); v3 = gelu_tanh(v3);
                }
                __nv_bfloat16* dst = (SEL == 1) ? g_gl : g_u;
                __nv_bfloat162 p0, p1;
                p0.x = __float2bfloat16(v0); p0.y = __float2bfloat16(v1);
                p1.x = __float2bfloat16(v2); p1.y = __float2bfloat16(v3);
                *reinterpret_cast<__nv_bfloat162*>(dst + (size_t)row*CHD + col) = p0;
                *reinterpret_cast<__nv_bfloat162*>(dst + (size_t)(row + 8)*CHD + col) = p1;
            } else {
                float b0 = bias[col], b1v = bias[col + 1];
                const float2 x0 = *reinterpret_cast<const float2*>(xres + (size_t)row*CDIM + col);
                const float2 x1 = *reinterpret_cast<const float2*>(xres + (size_t)(row + 8)*CDIM + col);
                float2 o0, o1;
                o0.x = 0.5f*(c0 + b0)  + 0.5f*x0.x;
                o0.y = 0.5f*(c1 + b1v) + 0.5f*x0.y;
                o1.x = 0.5f*(c2 + b0)  + 0.5f*x1.x;
                o1.y = 0.5f*(c3 + b1v) + 0.5f*x1.y;
                *reinterpret_cast<float2*>(outF + (size_t)row*CDIM + col) = o0;
                *reinterpret_cast<float2*>(outF + (size_t)(row + 8)*CDIM + col) = o1;
            }
        }
    }
}

// ---------------- launch ----------------
extern "C" void kernel_launch(void* const* d_in, const int* in_sizes, int n_in,
                              void* d_out, int out_size) {
    const float* x    = (const float*)d_in[0];
    const float* ln_g = (const float*)d_in[1];
    const float* ln_b = (const float*)d_in[2];
    const float* Wd   = (const float*)d_in[3];
    const float* bd   = (const float*)d_in[4];
    const float* Wg   = (const float*)d_in[5];
    const float* bg   = (const float*)d_in[6];
    const float* dw_w = (const float*)d_in[7];
    const float* dw_b = (const float*)d_in[8];
    const float* W1   = (const float*)d_in[9];
    const float* b1   = (const float*)d_in[10];
    const float* W2   = (const float*)d_in[11];
    const float* b2   = (const float*)d_in[12];
    // d_in[13..16]: Wq, bq, Wk, bk — dead (softmax over 1 key == 1)
    const float* Wv   = (const float*)d_in[17];
    const float* bv   = (const float*)d_in[18];
    const float* Wo   = (const float*)d_in[19];
    const float* bo   = (const float*)d_in[20];
    const float* Wu   = (const float*)d_in[21];
    const float* bu   = (const float*)d_in[22];
    const float* Wld  = (const float*)d_in[23];
    const float* Wlu  = (const float*)d_in[24];
    float* out = (float*)d_out;

    cudaFuncSetAttribute(gemm_k<0>, cudaFuncAttributeMaxDynamicSharedMemorySize, SMEM_BYTES);
    cudaFuncSetAttribute(gemm_k<1>, cudaFuncAttributeMaxDynamicSharedMemorySize, SMEM_BYTES);
    cudaFuncSetAttribute(gemm_k<2>, cudaFuncAttributeMaxDynamicSharedMemorySize, SMEM_BYTES);
    cudaFuncSetAttribute(gemm_k<3>, cudaFuncAttributeMaxDynamicSharedMemorySize, SMEM_BYTES);

    fold1<<<F1_GRID, 256>>>(Wd, Wg, dw_w, dw_b, W1, b1, Wv, Wo, Wu, Wld, bu, bd, bg, bv, bo);
    fold2<<<F2_GRID, 256>>>(W2, Wu, Wlu, bu, b2);

    ln_k<<<BDIM, 256>>>(x, ln_g, ln_b);
    gemm_k<0><<<dim3(NDGI/128, BDIM/128), 256, SMEM_BYTES>>>(nullptr, nullptr);
    gemm_k<1><<<dim3(CHD/128,  BDIM/128), 256, SMEM_BYTES>>>(nullptr, nullptr);
    gemm_k<2><<<dim3(CHD/128,  BDIM/128), 256, SMEM_BYTES>>>(nullptr, nullptr);
    gemm_k<3><<<dim3(CDIM/128, BDIM/128), 256, SMEM_BYTES>>>(out, x);
}